// round 13
// baseline (speedup 1.0000x reference)
#include <cuda_runtime.h>
#include <math.h>
#include <stdint.h>

#define BB 4
#define CC 64
#define LL 16384
#define BL 65536
#define DI 128
#define DS 16
#define NKF 65
#define NIMG 256
#define NCHK 64
#define CHKS 256
#define FPIX (NKF*128)   // 8320 freq pixels per image

__device__ float d_xz [BL*256];
__device__ float d_xc [BL*DI];
__device__ float d_dbc[BL*36];
__device__ float d_dt [BL*DI];
__device__ float d_hloc[BB*DI*NCHK*DS];
__device__ float d_cd  [BB*DI*NCHK];
__device__ float d_Hst [BB*DI*NCHK*DS];
__device__ float d_ygt [BB*DI*LL];
__device__ float d_xsp [BB*CC*LL];
__device__ float d_RT  [32768*130];
__device__ float d_Cre [NIMG*FPIX];
__device__ float d_Cim [NIMG*FPIX];
__device__ float d_mag [NIMG*FPIX];
__device__ float d_M1  [NIMG*FPIX];
__device__ float d_M2  [NIMG*FPIX];
__device__ float d_Zr  [NIMG*FPIX];
__device__ float d_Zi  [NIMG*FPIX];
__device__ float d_Yr  [NIMG*FPIX];
__device__ float d_Yi  [NIMG*FPIX];
__device__ float d_xfr [BB*CC*LL];
__device__ float d_TW1 [128*130];
__device__ float d_TCOS[128*128];
__device__ float d_TSIN[128*128];
__device__ float d_TSINN[128*128];
__device__ float d_IRW1[NKF*128];
__device__ float d_IRW2[NKF*128];

__global__ void gen_tables() {
    int i = blockIdx.x*256 + threadIdx.x;
    if (i < 128*130) {
        int w = i/130, j = i%130;
        int k = (j < NKF) ? j : j-NKF;
        float s,c; sincospif((float)((w*k)&127)/64.0f, &s, &c);
        d_TW1[i] = (j < NKF) ? c : -s;
    }
    if (i < 128*128) {
        int u = i/128, h = i%128;
        float s,c; sincospif((float)((u*h)&127)/64.0f, &s, &c);
        d_TCOS[i]=c; d_TSIN[i]=s; d_TSINN[i]=-s;
    }
    if (i < NKF*128) {
        int kf = i/128, w = i%128;
        float a = (kf==0 || kf==64) ? 1.0f : 2.0f;
        float s,c; sincospif((float)((kf*w)&127)/64.0f, &s, &c);
        d_IRW1[i] =  a*c*(1.0f/16384.0f);
        d_IRW2[i] = -a*s*(1.0f/16384.0f);
    }
}

// ---------------------------------------------------------------------------
// 3xTF32 tensor-core GEMM, interleaved hi/lo smem, dependency-spread MMAs.
// C[m,n] = sum_k A[m,k]*B[k,n] (+ A2*B2 if DUAL)
// 256 threads = 8 warps, warp tile 32x32 = 2x4 m16n8k8 fragments.
// ---------------------------------------------------------------------------
__device__ __forceinline__ uint32_t f2tf(float x) {
    uint32_t u; asm("cvt.rna.tf32.f32 %0, %1;" : "=r"(u) : "f"(x)); return u;
}
__device__ __forceinline__ void mma8(float* c, const uint32_t* a, const uint32_t* b) {
    asm volatile("mma.sync.aligned.m16n8k8.row.col.f32.tf32.tf32.f32 "
                 "{%0,%1,%2,%3}, {%4,%5,%6,%7}, {%8,%9}, {%0,%1,%2,%3};\n"
                 : "+f"(c[0]), "+f"(c[1]), "+f"(c[2]), "+f"(c[3])
                 : "r"(a[0]), "r"(a[1]), "r"(a[2]), "r"(a[3]),
                   "r"(b[0]), "r"(b[1]));
}

template<int BM, int BN, int BK, int WGN, bool DUAL>
__global__ void __launch_bounds__(256, 2)
tgemm(const float* __restrict__ A, const float* __restrict__ A2,
      int lda_m, int lda_k, int sA,
      const float* __restrict__ B, const float* __restrict__ B2,
      int ldb_k, int ldb_n, int sB,
      float* __restrict__ C, int ldc, int sC,
      int M, int N, int K,
      const float* __restrict__ bias, int biasMode, int doRelu)
{
    constexpr int PA = BM + 4, PB = BN + 4;
    constexpr int BKS = (BK == 16) ? 4 : 3;
    __shared__ uint2 As1[DUAL?1:BK][DUAL?1:PA];
    __shared__ uint2 Bs1[DUAL?1:BK][DUAL?1:PB];
    __shared__ uint4 As2[DUAL?BK:1][DUAL?PA:1];
    __shared__ uint4 Bs2[DUAL?BK:1][DUAL?PB:1];

    int bz = blockIdx.z;
    const float* Abp = A  + (size_t)bz*sA;
    const float* Bbp = B  + (size_t)bz*sB;
    const float* A2p = DUAL ? (A2 + (size_t)bz*sA) : A;
    const float* B2p = DUAL ? (B2 + (size_t)bz*sB) : B;
    float* Cb = C + (size_t)bz*sC;

    int m0 = blockIdx.y*BM, n0 = blockIdx.x*BN;
    int tid = threadIdx.x;
    int warp = tid >> 5, lane = tid & 31;
    int g = lane >> 2, q = lane & 3;
    int m_warp = (warp / WGN) * 32;
    int n_warp = (warp % WGN) * 32;

    float acc[2][4][4];
#pragma unroll
    for (int i=0;i<2;i++)
#pragma unroll
        for (int j=0;j<4;j++)
#pragma unroll
            for (int e=0;e<4;e++) acc[i][j][e] = 0.f;

    for (int k0 = 0; k0 < K; k0 += BK) {
        // ---- global -> smem with hi/lo split (interleaved) ----
        if (lda_k == 1) {
#pragma unroll
            for (int r = 0; r < BM*BK/256; r++) {
                int idx = tid + r*256;
                int k = idx & (BK-1), m = idx >> BKS;
                int gm = m0+m, gk = k0+k;
                bool ok = (gm < M) && (gk < K);
                float v = ok ? Abp[(size_t)gm*lda_m + gk] : 0.f;
                uint32_t h = f2tf(v);
                uint32_t l = f2tf(v - __uint_as_float(h));
                if (DUAL) {
                    float v2 = ok ? A2p[(size_t)gm*lda_m + gk] : 0.f;
                    uint32_t h2 = f2tf(v2);
                    As2[k][m] = make_uint4(h, l, h2, f2tf(v2 - __uint_as_float(h2)));
                } else {
                    As1[k][m] = make_uint2(h, l);
                }
            }
        } else {
#pragma unroll
            for (int r = 0; r < BM*BK/256; r++) {
                int idx = tid + r*256;
                int m = idx & (BM-1), k = idx / BM;
                int gm = m0+m, gk = k0+k;
                bool ok = (gm < M) && (gk < K);
                float v = ok ? Abp[(size_t)gm*lda_m + (size_t)gk*lda_k] : 0.f;
                uint32_t h = f2tf(v);
                uint32_t l = f2tf(v - __uint_as_float(h));
                if (DUAL) {
                    float v2 = ok ? A2p[(size_t)gm*lda_m + (size_t)gk*lda_k] : 0.f;
                    uint32_t h2 = f2tf(v2);
                    As2[k][m] = make_uint4(h, l, h2, f2tf(v2 - __uint_as_float(h2)));
                } else {
                    As1[k][m] = make_uint2(h, l);
                }
            }
        }
        if (ldb_n == 1) {
#pragma unroll
            for (int r = 0; r < BN*BK/256; r++) {
                int idx = tid + r*256;
                int n = idx & (BN-1), k = idx / BN;
                int gn = n0+n, gk = k0+k;
                bool ok = (gk < K) && (gn < N);
                float v = ok ? Bbp[(size_t)gk*ldb_k + gn] : 0.f;
                uint32_t h = f2tf(v);
                uint32_t l = f2tf(v - __uint_as_float(h));
                if (DUAL) {
                    float v2 = ok ? B2p[(size_t)gk*ldb_k + gn] : 0.f;
                    uint32_t h2 = f2tf(v2);
                    Bs2[k][n] = make_uint4(h, l, h2, f2tf(v2 - __uint_as_float(h2)));
                } else {
                    Bs1[k][n] = make_uint2(h, l);
                }
            }
        } else {
#pragma unroll
            for (int r = 0; r < BN*BK/256; r++) {
                int idx = tid + r*256;
                int k = idx & (BK-1), n = idx >> BKS;
                int gn = n0+n, gk = k0+k;
                bool ok = (gk < K) && (gn < N);
                float v = ok ? Bbp[(size_t)gk*ldb_k + (size_t)gn*ldb_n] : 0.f;
                uint32_t h = f2tf(v);
                uint32_t l = f2tf(v - __uint_as_float(h));
                if (DUAL) {
                    float v2 = ok ? B2p[(size_t)gk*ldb_k + (size_t)gn*ldb_n] : 0.f;
                    uint32_t h2 = f2tf(v2);
                    Bs2[k][n] = make_uint4(h, l, h2, f2tf(v2 - __uint_as_float(h2)));
                } else {
                    Bs1[k][n] = make_uint2(h, l);
                }
            }
        }
        __syncthreads();

        if (!DUAL) {
            uint32_t ah[2][2][4], al[2][2][4], bh[2][4][2], bl[2][4][2];
#define LOADF(K8, BUF) { \
    _Pragma("unroll") \
    for (int mt=0; mt<2; mt++) { int mA = m_warp + mt*16; \
        uint2 v0 = As1[(K8)+q  ][mA+g  ]; \
        uint2 v1 = As1[(K8)+q  ][mA+g+8]; \
        uint2 v2 = As1[(K8)+q+4][mA+g  ]; \
        uint2 v3 = As1[(K8)+q+4][mA+g+8]; \
        ah[BUF][mt][0]=v0.x; al[BUF][mt][0]=v0.y; \
        ah[BUF][mt][1]=v1.x; al[BUF][mt][1]=v1.y; \
        ah[BUF][mt][2]=v2.x; al[BUF][mt][2]=v2.y; \
        ah[BUF][mt][3]=v3.x; al[BUF][mt][3]=v3.y; } \
    _Pragma("unroll") \
    for (int nt=0; nt<4; nt++) { int nB = n_warp + nt*8; \
        uint2 w0 = Bs1[(K8)+q  ][nB+g]; \
        uint2 w1 = Bs1[(K8)+q+4][nB+g]; \
        bh[BUF][nt][0]=w0.x; bl[BUF][nt][0]=w0.y; \
        bh[BUF][nt][1]=w1.x; bl[BUF][nt][1]=w1.y; } }

            LOADF(0, 0)
#pragma unroll
            for (int s = 0; s < BK/8; s++) {
                if (s+1 < BK/8) { LOADF((s+1)*8, (s+1)&1) }
                const int b = s & 1;
#pragma unroll
                for (int mt=0; mt<2; mt++)
#pragma unroll
                    for (int nt=0; nt<4; nt++) mma8(acc[mt][nt], al[b][mt], bh[b][nt]);
#pragma unroll
                for (int mt=0; mt<2; mt++)
#pragma unroll
                    for (int nt=0; nt<4; nt++) mma8(acc[mt][nt], ah[b][mt], bl[b][nt]);
#pragma unroll
                for (int mt=0; mt<2; mt++)
#pragma unroll
                    for (int nt=0; nt<4; nt++) mma8(acc[mt][nt], ah[b][mt], bh[b][nt]);
            }
#undef LOADF
        } else {
            // DUAL: BK=8, one k8 step; all frags loaded up front.
            uint4 fB[4][2];
#pragma unroll
            for (int nt=0; nt<4; nt++) { int nB = n_warp + nt*8;
                fB[nt][0] = Bs2[q  ][nB+g];
                fB[nt][1] = Bs2[q+4][nB+g]; }
            uint4 fA[2][4];
#pragma unroll
            for (int mt=0; mt<2; mt++) { int mA = m_warp + mt*16;
                fA[mt][0] = As2[q  ][mA+g  ];
                fA[mt][1] = As2[q  ][mA+g+8];
                fA[mt][2] = As2[q+4][mA+g  ];
                fA[mt][3] = As2[q+4][mA+g+8]; }
#pragma unroll
            for (int mt=0; mt<2; mt++) {
                uint32_t a1h[4]={fA[mt][0].x,fA[mt][1].x,fA[mt][2].x,fA[mt][3].x};
                uint32_t a1l[4]={fA[mt][0].y,fA[mt][1].y,fA[mt][2].y,fA[mt][3].y};
                uint32_t a2h[4]={fA[mt][0].z,fA[mt][1].z,fA[mt][2].z,fA[mt][3].z};
                uint32_t a2l[4]={fA[mt][0].w,fA[mt][1].w,fA[mt][2].w,fA[mt][3].w};
#pragma unroll
                for (int nt=0; nt<4; nt++) { uint32_t b0[2]={fB[nt][0].x,fB[nt][1].x}; mma8(acc[mt][nt], a1l, b0); }
#pragma unroll
                for (int nt=0; nt<4; nt++) { uint32_t b0[2]={fB[nt][0].y,fB[nt][1].y}; mma8(acc[mt][nt], a1h, b0); }
#pragma unroll
                for (int nt=0; nt<4; nt++) { uint32_t b0[2]={fB[nt][0].x,fB[nt][1].x}; mma8(acc[mt][nt], a1h, b0); }
#pragma unroll
                for (int nt=0; nt<4; nt++) { uint32_t b0[2]={fB[nt][0].z,fB[nt][1].z}; mma8(acc[mt][nt], a2l, b0); }
#pragma unroll
                for (int nt=0; nt<4; nt++) { uint32_t b0[2]={fB[nt][0].w,fB[nt][1].w}; mma8(acc[mt][nt], a2h, b0); }
#pragma unroll
                for (int nt=0; nt<4; nt++) { uint32_t b0[2]={fB[nt][0].z,fB[nt][1].z}; mma8(acc[mt][nt], a2h, b0); }
            }
        }
        __syncthreads();
    }
    // ---- epilogue ----
#pragma unroll
    for (int mt=0; mt<2; mt++) {
#pragma unroll
        for (int nt=0; nt<4; nt++) {
            int mbase = m0 + m_warp + mt*16 + g;
            int nbase = n0 + n_warp + nt*8 + q*2;
#pragma unroll
            for (int e=0; e<4; e++) {
                int m = mbase + ((e >= 2) ? 8 : 0);
                int n = nbase + (e & 1);
                if (m < M && n < N) {
                    float v = acc[mt][nt][e];
                    if (biasMode == 1) v += bias[n];
                    else if (biasMode == 2) v += bias[m];
                    if (doRelu) v = fmaxf(v, 0.f);
                    Cb[(size_t)m*ldc + n] = v;
                }
            }
        }
    }
}

// Nyquist column (kf=64) of the 65-wide complex stages, exact fp32:
// out[img*sC + u*65 + 64] = sum_k A1[u*128+k]*B1[img*sB + k*ldb] + A2[u*128+k]*B2[img*sB + k*ldb]
__global__ void nyq_k(const float* __restrict__ A1, const float* __restrict__ A2,
                      const float* __restrict__ B1, const float* __restrict__ B2,
                      int ldb, int sB, float* __restrict__ out, int sC)
{
    int gid = blockIdx.x*256 + threadIdx.x;   // 32768 = 256 imgs * 128 u
    int img = gid >> 7, u = gid & 127;
    const float* b1 = B1 + (size_t)img*sB;
    const float* b2 = B2 + (size_t)img*sB;
    const float* a1 = A1 + u*128;
    const float* a2 = A2 + u*128;
    float s = 0.f;
#pragma unroll 4
    for (int k=0; k<128; k++)
        s += a1[k]*b1[(size_t)k*ldb] + a2[k]*b2[(size_t)k*ldb];
    out[(size_t)img*sC + u*65 + 64] = s;
}

// rfft columns 128,129 (imag kf=63,64 region of the 130-wide row transform)
__global__ void rfft_tail_k(const float* __restrict__ x, float* __restrict__ RT)
{
    int gid = blockIdx.x*256 + threadIdx.x;   // 65536 = 32768 rows * 2 cols
    int row = gid >> 1, j = 128 + (gid & 1);
    const float* xr = x + (size_t)row*128;
    float s = 0.f;
#pragma unroll 4
    for (int k=0; k<128; k++) s += xr[k]*d_TW1[k*130+j];
    RT[(size_t)row*130 + j] = s;
}

__global__ void conv_silu_k(const float* __restrict__ xz, const float* __restrict__ cw,
                            const float* __restrict__ cb, float* __restrict__ xc)
{
    int idx = blockIdx.x*256 + threadIdx.x;
    if (idx >= BL*DI) return;
    int d = idx & 127, bl = idx >> 7, l = bl & (LL-1);
    size_t base = (size_t)bl*256 + d;
    float acc = cb[d];
#pragma unroll
    for (int k=0;k<4;k++) {
        int lsrc = l - 3 + k;
        float v = (lsrc >= 0) ? xz[base + (size_t)(k-3)*256] : 0.f;
        acc = fmaf(cw[d*4+k], v, acc);
    }
    float sig = 1.f/(1.f+__expf(-acc));
    xc[idx] = acc*sig;
}

__global__ void dt_proj_k(const float* __restrict__ dbc, const float* __restrict__ Wdt,
                          const float* __restrict__ bdt, float* __restrict__ dt)
{
    int idx = blockIdx.x*256 + threadIdx.x;
    if (idx >= BL*DI) return;
    int d = idx & 127, bl = idx >> 7;
    const float* row = dbc + (size_t)bl*36;
    float s = bdt[d];
#pragma unroll
    for (int r=0;r<4;r++) s = fmaf(row[r], Wdt[r*128+d], s);
    dt[idx] = (s > 20.f) ? s : log1pf(__expf(s));
}

__global__ void scan1_k(const float* __restrict__ dt, const float* __restrict__ xc,
                        const float* __restrict__ dbc, const float* __restrict__ A_log,
                        float* __restrict__ hloc, float* __restrict__ cdout)
{
    int warp = threadIdx.x >> 5;
    int wg   = (blockIdx.x<<3) + warp;
    int lane = threadIdx.x & 31;
    int s = lane & 15, half = lane >> 4;
    int dpair = wg & 63, chunk = (wg>>6) & 63, b = wg>>12;
    int d = (dpair<<1) + half;
    float Aval = -__expf(A_log[d*16+s]);
    float h = 0.f, cd = 0.f;
    size_t rowbase = (size_t)b*LL + (chunk<<8);
    const float* dtp = dt  + rowbase*128 + d;
    const float* xcp = xc  + rowbase*128 + d;
    const float* bp  = dbc + rowbase*36 + 4 + s;
#pragma unroll 8
    for (int t=0;t<CHKS;t++) {
        float dtv = dtp[t*128], xcv = xcp[t*128], Bv = bp[t*36];
        h = fmaf(h, __expf(dtv*Aval), dtv*xcv*Bv);
        cd += dtv;
    }
    int cidx = (b*128+d)*NCHK + chunk;
    hloc[cidx*16+s] = h;
    if (s == 0 ) cdout[cidx] = cd;
}

__global__ void carry_k(const float* __restrict__ hloc, const float* __restrict__ cd,
                        const float* __restrict__ A_log, float* __restrict__ Hst)
{
    int idx = blockIdx.x*256 + threadIdx.x;
    if (idx >= BB*DI*DS) return;
    int s = idx & 15, d = (idx>>4)&127, b = idx>>11;
    float Aval = -__expf(A_log[d*16+s]);
    float H = 0.f;
    int base = (b*128+d)*NCHK;
    for (int c=0;c<NCHK;c++) {
        Hst[(base+c)*16+s] = H;
        H = fmaf(H, __expf(Aval*cd[base+c]), hloc[(base+c)*16+s]);
    }
}

__global__ void scan2_k(const float* __restrict__ dt, const float* __restrict__ xc,
                        const float* __restrict__ dbc, const float* __restrict__ A_log,
                        const float* __restrict__ Hst, const float* __restrict__ xz,
                        const float* __restrict__ Dvec, float* __restrict__ ygt)
{
    __shared__ float shy[8][2][CHKS];
    int warp = threadIdx.x >> 5;
    int wg   = (blockIdx.x<<3) + warp;
    int lane = threadIdx.x & 31;
    int s = lane & 15, half = lane >> 4;
    int dpair = wg & 63, chunk = (wg>>6) & 63, b = wg>>12;
    int d = (dpair<<1) + half;
    float Aval = -__expf(A_log[d*16+s]);
    float h = Hst[((b*128+d)*NCHK + chunk)*16 + s];
    float Dv = Dvec[d];
    int t0 = chunk<<8;
    size_t rowbase = (size_t)b*LL + t0;
    const float* dtp = dt  + rowbase*128 + d;
    const float* xcp = xc  + rowbase*128 + d;
    const float* bp  = dbc + rowbase*36 + 4 + s;
    const float* cp  = dbc + rowbase*36 + 20 + s;
    const float* zp  = xz  + rowbase*256 + 128 + d;
#pragma unroll 4
    for (int t=0;t<CHKS;t++) {
        float dtv = dtp[t*128], xcv = xcp[t*128], Bv = bp[t*36], Cv = cp[t*36];
        h = fmaf(h, __expf(dtv*Aval), dtv*xcv*Bv);
        float p = h*Cv;
        p += __shfl_xor_sync(0xffffffffu, p, 1);
        p += __shfl_xor_sync(0xffffffffu, p, 2);
        p += __shfl_xor_sync(0xffffffffu, p, 4);
        p += __shfl_xor_sync(0xffffffffu, p, 8);
        if (s == 0) {
            float zv = zp[(size_t)t*256];
            float y = fmaf(xcv, Dv, p);
            float sig = 1.f/(1.f+__expf(-zv));
            shy[warp][half][t] = y*zv*sig;
        }
    }
    __syncwarp();
#pragma unroll
    for (int r=0;r<2;r++) {
        int dd = (dpair<<1) + r;
        float* dst = ygt + ((size_t)b*128 + dd)*LL + t0;
        for (int t=lane;t<CHKS;t+=32) dst[t] = shy[warp][r][t];
    }
}

__global__ void mag_k(const float* __restrict__ re, const float* __restrict__ im,
                      float* __restrict__ mg)
{
    int i = blockIdx.x*256 + threadIdx.x;
    if (i >= NIMG*FPIX) return;
    float r = re[i], m = im[i];
    mg[i] = sqrtf(r*r + m*m);
}

__global__ void phase_k(const float* __restrict__ re, const float* __restrict__ im,
                        const float* __restrict__ mg, const float* __restrict__ M2,
                        float* __restrict__ Zr, float* __restrict__ Zi)
{
    int i = blockIdx.x*256 + threadIdx.x;
    if (i >= NIMG*FPIX) return;
    float m = mg[i], m2 = M2[i];
    if (m > 1e-20f) {
        float sc = m2/m;
        Zr[i] = re[i]*sc; Zi[i] = im[i]*sc;
    } else { Zr[i] = m2; Zi[i] = 0.f; }
}

__global__ void add_k(float* __restrict__ dst, const float* __restrict__ src)
{
    int i = blockIdx.x*256 + threadIdx.x;
    if (i < BB*CC*LL) dst[i] += src[i];
}

#define GR(BM,BN,M,N,batch) dim3(((N)+(BN)-1)/(BN), ((M)+(BM)-1)/(BM), (batch))

extern "C" void kernel_launch(void* const* d_in, const int* in_sizes, int n_in,
                              void* d_out, int out_size)
{
    const float* x      = (const float*)d_in[0];
    const float* W_in   = (const float*)d_in[1];
    const float* conv_w = (const float*)d_in[2];
    const float* conv_b = (const float*)d_in[3];
    const float* W_xproj= (const float*)d_in[4];
    const float* W_dt   = (const float*)d_in[5];
    const float* b_dt   = (const float*)d_in[6];
    const float* A_log  = (const float*)d_in[7];
    const float* Dvec   = (const float*)d_in[8];
    const float* W_out  = (const float*)d_in[9];
    const float* Wf1    = (const float*)d_in[10];
    const float* bf1    = (const float*)d_in[11];
    const float* Wf2    = (const float*)d_in[12];
    const float* bf2    = (const float*)d_in[13];
    const float* W_enh  = (const float*)d_in[14];
    const float* b_enh  = (const float*)d_in[15];
    const float* W_seg  = (const float*)d_in[16];
    const float* b_seg  = (const float*)d_in[17];
    float* out = (float*)d_out;

    void* pv;
    cudaGetSymbolAddress(&pv, d_xz);   float* p_xz  = (float*)pv;
    cudaGetSymbolAddress(&pv, d_xc);   float* p_xc  = (float*)pv;
    cudaGetSymbolAddress(&pv, d_dbc);  float* p_dbc = (float*)pv;
    cudaGetSymbolAddress(&pv, d_dt);   float* p_dt  = (float*)pv;
    cudaGetSymbolAddress(&pv, d_hloc); float* p_hl  = (float*)pv;
    cudaGetSymbolAddress(&pv, d_cd);   float* p_cd  = (float*)pv;
    cudaGetSymbolAddress(&pv, d_Hst);  float* p_Hs  = (float*)pv;
    cudaGetSymbolAddress(&pv, d_ygt);  float* p_yg  = (float*)pv;
    cudaGetSymbolAddress(&pv, d_xsp);  float* p_xsp = (float*)pv;
    cudaGetSymbolAddress(&pv, d_RT);   float* p_RT  = (float*)pv;
    cudaGetSymbolAddress(&pv, d_Cre);  float* p_Cre = (float*)pv;
    cudaGetSymbolAddress(&pv, d_Cim);  float* p_Cim = (float*)pv;
    cudaGetSymbolAddress(&pv, d_mag);  float* p_mag = (float*)pv;
    cudaGetSymbolAddress(&pv, d_M1);   float* p_M1  = (float*)pv;
    cudaGetSymbolAddress(&pv, d_M2);   float* p_M2  = (float*)pv;
    cudaGetSymbolAddress(&pv, d_Zr);   float* p_Zr  = (float*)pv;
    cudaGetSymbolAddress(&pv, d_Zi);   float* p_Zi  = (float*)pv;
    cudaGetSymbolAddress(&pv, d_Yr);   float* p_Yr  = (float*)pv;
    cudaGetSymbolAddress(&pv, d_Yi);   float* p_Yi  = (float*)pv;
    cudaGetSymbolAddress(&pv, d_xfr);  float* p_xfr = (float*)pv;
    cudaGetSymbolAddress(&pv, d_TW1);  float* p_TW1 = (float*)pv;
    cudaGetSymbolAddress(&pv, d_TCOS); float* p_TC  = (float*)pv;
    cudaGetSymbolAddress(&pv, d_TSIN); float* p_TS  = (float*)pv;
    cudaGetSymbolAddress(&pv, d_TSINN);float* p_TSN = (float*)pv;
    cudaGetSymbolAddress(&pv, d_IRW1); float* p_I1  = (float*)pv;
    cudaGetSymbolAddress(&pv, d_IRW2); float* p_I2  = (float*)pv;

    gen_tables<<<65, 256>>>();

    // ---- Mamba branch ----
    // xz[b] (L x 256) = xf[b] (L x 64) @ W_in
    tgemm<128,64,16,2,false><<<GR(128,64,LL,256,BB),256>>>(
        x,0, 1, LL, CC*LL,  W_in,0, 256,1, 0,  p_xz, 256, LL*256,  LL, 256, CC, 0,0,0);
    conv_silu_k<<<(BL*DI+255)/256,256>>>(p_xz, conv_w, conv_b, p_xc);
    // dbc (BL x 36) = xc (BL x 128) @ W_xproj
    tgemm<128,64,16,2,false><<<GR(128,64,BL,36,1),256>>>(
        p_xc,0, 128,1,0,  W_xproj,0, 36,1,0,  p_dbc, 36,0,  BL, 36, 128, 0,0,0);
    dt_proj_k<<<(BL*DI+255)/256,256>>>(p_dbc, W_dt, b_dt, p_dt);
    scan1_k<<<2048,256>>>(p_dt, p_xc, p_dbc, A_log, p_hl, p_cd);
    carry_k<<<32,256>>>(p_hl, p_cd, A_log, p_Hs);
    scan2_k<<<2048,256>>>(p_dt, p_xc, p_dbc, A_log, p_Hs, p_xz, Dvec, p_yg);
    // x_spatial channel-major: xsp[b](64 x L) = W_out^T @ ygt[b](128 x L)
    tgemm<64,128,16,4,false><<<GR(64,128,CC,LL,BB),256>>>(
        W_out,0, 1, CC, 0,  p_yg,0, LL,1, DI*LL,  p_xsp, LL, CC*LL,  CC, LL, DI, 0,0,0);

    // ---- Frequency branch (DFT GEMMs) ----
    // row rfft: RT (32768 x 128) = x (32768 x 128) @ TW1[:, :128]; cols 128-129 via tail kernel
    tgemm<128,64,16,2,false><<<GR(128,64,32768,128,1),256>>>(
        x,0, 128,1,0,  p_TW1,0, 130,1,0,  p_RT, 130,0,  32768, 128, 128, 0,0,0);
    rfft_tail_k<<<256,256>>>(x, p_RT);
    // column FFT per image (N=64 main + Nyquist col via nyq_k):
    tgemm<128,64,8,2,true><<<GR(128,64,128,64,NIMG),256>>>(
        p_TC, p_TS,  128,1,0,  p_RT, p_RT+65, 130,1, 128*130,  p_Cre, NKF, FPIX,  128, 64, 128, 0,0,0);
    tgemm<128,64,8,2,true><<<GR(128,64,128,64,NIMG),256>>>(
        p_TC, p_TSN, 128,1,0,  p_RT+65, p_RT, 130,1, 128*130,  p_Cim, NKF, FPIX,  128, 64, 128, 0,0,0);
    nyq_k<<<128,256>>>(p_TC, p_TS,  p_RT+64,  p_RT+129, 130, 128*130, p_Cre, FPIX);
    nyq_k<<<128,256>>>(p_TC, p_TSN, p_RT+129, p_RT+64,  130, 128*130, p_Cim, FPIX);
    mag_k<<<(NIMG*FPIX+255)/256,256>>>(p_Cre, p_Cim, p_mag);
    // channel mix per batch: M1 = relu(Wf1 @ mag + bf1); M2 = Wf2 @ M1 + bf2
    tgemm<64,128,16,4,false><<<GR(64,128,CC,FPIX,BB),256>>>(
        Wf1,0, CC,1,0,  p_mag,0, FPIX,1, CC*FPIX,  p_M1, FPIX, CC*FPIX,  CC, FPIX, CC, bf1, 2, 1);
    tgemm<64,128,16,4,false><<<GR(64,128,CC,FPIX,BB),256>>>(
        Wf2,0, CC,1,0,  p_M1,0,  FPIX,1, CC*FPIX,  p_M2, FPIX, CC*FPIX,  CC, FPIX, CC, bf2, 2, 0);
    phase_k<<<(NIMG*FPIX+255)/256,256>>>(p_Cre, p_Cim, p_mag, p_M2, p_Zr, p_Zi);
    // inverse column FFT (N=64 main + Nyquist col):
    tgemm<128,64,8,2,true><<<GR(128,64,128,64,NIMG),256>>>(
        p_TC, p_TSN, 128,1,0,  p_Zr, p_Zi, NKF,1, FPIX,  p_Yr, NKF, FPIX,  128, 64, 128, 0,0,0);
    tgemm<128,64,8,2,true><<<GR(128,64,128,64,NIMG),256>>>(
        p_TS, p_TC,  128,1,0,  p_Zr, p_Zi, NKF,1, FPIX,  p_Yi, NKF, FPIX,  128, 64, 128, 0,0,0);
    nyq_k<<<128,256>>>(p_TC, p_TSN, p_Zr+64, p_Zi+64, NKF, FPIX, p_Yr, FPIX);
    nyq_k<<<128,256>>>(p_TS, p_TC,  p_Zr+64, p_Zi+64, NKF, FPIX, p_Yi, FPIX);
    // irfft rows: xfr = Yr@IRW1 + Yi@IRW2   (per image, M=128 h, N=128 w, K=65)
    tgemm<128,64,8,2,true><<<GR(128,64,128,128,NIMG),256>>>(
        p_Yr, p_Yi, NKF,1, FPIX,  p_I1, p_I2, 128,1, 0,  p_xfr, 128, LL,  128, 128, NKF, 0,0,0);

    // ---- Fuse + heads ----
    add_k<<<(BB*CC*LL+255)/256,256>>>(p_xfr, p_xsp);
    tgemm<64,128,16,4,false><<<GR(64,128,CC,LL,BB),256>>>(
        W_enh,0, CC,1,0,  p_xfr,0, LL,1, CC*LL,  out,            LL, CC*LL,  CC, LL, CC, b_enh, 2, 0);
    tgemm<64,128,16,4,false><<<GR(64,128,CC,LL,BB),256>>>(
        W_seg,0, CC,1,0,  p_xfr,0, LL,1, CC*LL,  out + BB*CC*LL, LL, CC*LL,  CC, LL, CC, b_seg, 2, 0);
}

// round 14
// speedup vs baseline: 1.1771x; 1.1771x over previous
#include <cuda_runtime.h>
#include <math.h>

#define BB 4
#define CC 64
#define LL 16384
#define BL 65536
#define DI 128
#define DS 16
#define NKF 65
#define NIMG 256
#define NCHK 64
#define CHKS 256
#define FPIX (NKF*128)   // 8320 freq pixels per image

__device__ float d_xz [BL*256];
__device__ float d_xc [BL*DI];
__device__ float d_dbc[BL*36];
__device__ float d_dt [BL*DI];
__device__ float d_hloc[BB*DI*NCHK*DS];
__device__ float d_cd  [BB*DI*NCHK];
__device__ float d_Hst [BB*DI*NCHK*DS];
__device__ float d_ygt [BB*DI*LL];
__device__ float d_xsp [BB*CC*LL];
__device__ float d_RT  [32768*130];
__device__ float d_Cre [NIMG*FPIX];
__device__ float d_Cim [NIMG*FPIX];
__device__ float d_mag [NIMG*FPIX];
__device__ float d_M1  [NIMG*FPIX];
__device__ float d_M2  [NIMG*FPIX];
__device__ float d_Zr  [NIMG*FPIX];
__device__ float d_Zi  [NIMG*FPIX];
__device__ float d_Yr  [NIMG*FPIX];
__device__ float d_Yi  [NIMG*FPIX];
__device__ float d_xfr [BB*CC*LL];
__device__ float d_TW1 [128*130];
__device__ float d_TCOS[128*128];
__device__ float d_TSIN[128*128];
__device__ float d_TSINN[128*128];
__device__ float d_IRW1[NKF*128];
__device__ float d_IRW2[NKF*128];

__global__ void gen_tables() {
    int i = blockIdx.x*256 + threadIdx.x;
    if (i < 128*130) {
        int w = i/130, j = i%130;
        int k = (j < NKF) ? j : j-NKF;
        float s,c; sincospif((float)((w*k)&127)/64.0f, &s, &c);
        d_TW1[i] = (j < NKF) ? c : -s;
    }
    if (i < 128*128) {
        int u = i/128, h = i%128;
        float s,c; sincospif((float)((u*h)&127)/64.0f, &s, &c);
        d_TCOS[i]=c; d_TSIN[i]=s; d_TSINN[i]=-s;
    }
    if (i < NKF*128) {
        int kf = i/128, w = i%128;
        float a = (kf==0 || kf==64) ? 1.0f : 2.0f;
        float s,c; sincospif((float)((kf*w)&127)/64.0f, &s, &c);
        d_IRW1[i] =  a*c*(1.0f/16384.0f);
        d_IRW2[i] = -a*s*(1.0f/16384.0f);
    }
}

// C[m,n] = sum_k A[m,k]*B[k,n] (+ A2[m,k]*B2[k,n] if DUAL)
// biasMode: 0=none, 1=bias[n], 2=bias[m], 3=residual matrix add (bias has C layout)
template<bool DUAL>
__global__ void sgemm(const float* __restrict__ A, const float* __restrict__ A2,
                      int lda_m, int lda_k, int sA,
                      const float* __restrict__ B, const float* __restrict__ B2,
                      int ldb_k, int ldb_n, int sB,
                      float* __restrict__ C, int ldc, int sC,
                      int M, int N, int K,
                      const float* __restrict__ bias, int biasMode, int doRelu)
{
    __shared__ float As[16][68], Bs[16][68], As2[16][68], Bs2[16][68];
    int bz = blockIdx.z;
    const float* Ab  = A + (size_t)bz*sA;
    const float* Bb  = B + (size_t)bz*sB;
    const float* A2b = DUAL ? (A2 + (size_t)bz*sA) : A;
    const float* B2b = DUAL ? (B2 + (size_t)bz*sB) : B;
    float* Cb = C + (size_t)bz*sC;
    int m0 = blockIdx.y<<6, n0 = blockIdx.x<<6;
    int tid = threadIdx.x, tx = tid&15, ty = tid>>4;
    float acc[4][4];
#pragma unroll
    for (int i=0;i<4;i++)
#pragma unroll
        for (int j=0;j<4;j++) acc[i][j]=0.f;

    for (int k0 = 0; k0 < K; k0 += 16) {
        if (lda_k == 1) {
            int kl = tid&15, ml0 = tid>>4;
#pragma unroll
            for (int i=0;i<4;i++) {
                int ml = ml0 + (i<<4), m = m0+ml, k = k0+kl;
                bool ok = (m<M)&&(k<K);
                As[kl][ml] = ok ? Ab[(size_t)m*lda_m + k] : 0.f;
                if (DUAL) As2[kl][ml] = ok ? A2b[(size_t)m*lda_m + k] : 0.f;
            }
        } else {
            int ml = tid&63, kl0 = tid>>6;
#pragma unroll
            for (int i=0;i<4;i++) {
                int kl = kl0 + (i<<2), m = m0+ml, k = k0+kl;
                bool ok = (m<M)&&(k<K);
                As[kl][ml] = ok ? Ab[(size_t)m*lda_m + (size_t)k*lda_k] : 0.f;
                if (DUAL) As2[kl][ml] = ok ? A2b[(size_t)m*lda_m + (size_t)k*lda_k] : 0.f;
            }
        }
        if (ldb_n == 1) {
            int nl = tid&63, kl0 = tid>>6;
#pragma unroll
            for (int i=0;i<4;i++) {
                int kl = kl0 + (i<<2), n = n0+nl, k = k0+kl;
                bool ok = (k<K)&&(n<N);
                Bs[kl][nl] = ok ? Bb[(size_t)k*ldb_k + n] : 0.f;
                if (DUAL) Bs2[kl][nl] = ok ? B2b[(size_t)k*ldb_k + n] : 0.f;
            }
        } else {
            int kl = tid&15, nl0 = tid>>4;
#pragma unroll
            for (int i=0;i<4;i++) {
                int nl = nl0 + (i<<4), n = n0+nl, k = k0+kl;
                bool ok = (k<K)&&(n<N);
                Bs[kl][nl] = ok ? Bb[(size_t)k*ldb_k + (size_t)n*ldb_n] : 0.f;
                if (DUAL) Bs2[kl][nl] = ok ? B2b[(size_t)k*ldb_k + (size_t)n*ldb_n] : 0.f;
            }
        }
        __syncthreads();
#pragma unroll
        for (int kk=0; kk<16; kk++) {
            float4 av = *(const float4*)&As[kk][ty<<2];
            float4 bv = *(const float4*)&Bs[kk][tx<<2];
            float a[4]={av.x,av.y,av.z,av.w}, b[4]={bv.x,bv.y,bv.z,bv.w};
#pragma unroll
            for (int i=0;i<4;i++)
#pragma unroll
                for (int j=0;j<4;j++) acc[i][j] = fmaf(a[i], b[j], acc[i][j]);
            if (DUAL) {
                float4 av2 = *(const float4*)&As2[kk][ty<<2];
                float4 bv2 = *(const float4*)&Bs2[kk][tx<<2];
                float a2[4]={av2.x,av2.y,av2.z,av2.w}, b2[4]={bv2.x,bv2.y,bv2.z,bv2.w};
#pragma unroll
                for (int i=0;i<4;i++)
#pragma unroll
                    for (int j=0;j<4;j++) acc[i][j] = fmaf(a2[i], b2[j], acc[i][j]);
            }
        }
        __syncthreads();
    }
#pragma unroll
    for (int i=0;i<4;i++) {
        int m = m0 + (ty<<2) + i;
        if (m >= M) continue;
#pragma unroll
        for (int j=0;j<4;j++) {
            int n = n0 + (tx<<2) + j;
            if (n >= N) continue;
            float v = acc[i][j];
            if (biasMode == 1) v += bias[n];
            else if (biasMode == 2) v += bias[m];
            else if (biasMode == 3) v += bias[(size_t)bz*sC + (size_t)m*ldc + n];
            if (doRelu) v = fmaxf(v, 0.f);
            Cb[(size_t)m*ldc + n] = v;
        }
    }
}

// Nyquist column (kf=64) of the 65-wide complex stages, exact fp32, warp-per-output.
__global__ void nyq_k(const float* __restrict__ A1, const float* __restrict__ A2,
                      const float* __restrict__ B1, const float* __restrict__ B2,
                      int ldb, int sB, float* __restrict__ out, int sC)
{
    int w = (blockIdx.x*256 + threadIdx.x) >> 5;   // 4096 blocks * 8 warps = 32768 outputs
    int lane = threadIdx.x & 31;
    int img = w >> 7, u = w & 127;
    const float* b1 = B1 + (size_t)img*sB;
    const float* b2 = B2 + (size_t)img*sB;
    const float* a1 = A1 + u*128;
    const float* a2 = A2 + u*128;
    float s = 0.f;
#pragma unroll
    for (int kk=0; kk<4; kk++) {
        int k = lane + kk*32;
        s += a1[k]*b1[(size_t)k*ldb] + a2[k]*b2[(size_t)k*ldb];
    }
    s += __shfl_xor_sync(0xffffffffu, s, 16);
    s += __shfl_xor_sync(0xffffffffu, s, 8);
    s += __shfl_xor_sync(0xffffffffu, s, 4);
    s += __shfl_xor_sync(0xffffffffu, s, 2);
    s += __shfl_xor_sync(0xffffffffu, s, 1);
    if (lane == 0) out[(size_t)img*sC + u*65 + 64] = s;
}

// rfft columns 128,129 of the 130-wide row transform, warp-per-output.
__global__ void rfft_tail_k(const float* __restrict__ x, float* __restrict__ RT)
{
    int w = (blockIdx.x*256 + threadIdx.x) >> 5;   // 8192 blocks * 8 warps = 65536 outputs
    int lane = threadIdx.x & 31;
    int row = w >> 1, j = 128 + (w & 1);
    const float* xr = x + (size_t)row*128;
    float s = 0.f;
#pragma unroll
    for (int kk=0; kk<4; kk++) {
        int k = lane + kk*32;
        s += xr[k]*d_TW1[k*130+j];
    }
    s += __shfl_xor_sync(0xffffffffu, s, 16);
    s += __shfl_xor_sync(0xffffffffu, s, 8);
    s += __shfl_xor_sync(0xffffffffu, s, 4);
    s += __shfl_xor_sync(0xffffffffu, s, 2);
    s += __shfl_xor_sync(0xffffffffu, s, 1);
    if (lane == 0) RT[(size_t)row*130 + j] = s;
}

__global__ void conv_silu_k(const float* __restrict__ xz, const float* __restrict__ cw,
                            const float* __restrict__ cb, float* __restrict__ xc)
{
    int idx = blockIdx.x*256 + threadIdx.x;
    if (idx >= BL*DI) return;
    int d = idx & 127, bl = idx >> 7, l = bl & (LL-1);
    size_t base = (size_t)bl*256 + d;
    float acc = cb[d];
#pragma unroll
    for (int k=0;k<4;k++) {
        int lsrc = l - 3 + k;
        float v = (lsrc >= 0) ? xz[base + (size_t)(k-3)*256] : 0.f;
        acc = fmaf(cw[d*4+k], v, acc);
    }
    float sig = 1.f/(1.f+__expf(-acc));
    xc[idx] = acc*sig;
}

__global__ void dt_proj_k(const float* __restrict__ dbc, const float* __restrict__ Wdt,
                          const float* __restrict__ bdt, float* __restrict__ dt)
{
    int idx = blockIdx.x*256 + threadIdx.x;
    if (idx >= BL*DI) return;
    int d = idx & 127, bl = idx >> 7;
    const float* row = dbc + (size_t)bl*36;
    float s = bdt[d];
#pragma unroll
    for (int r=0;r<4;r++) s = fmaf(row[r], Wdt[r*128+d], s);
    dt[idx] = (s > 20.f) ? s : log1pf(__expf(s));
}

__global__ void scan1_k(const float* __restrict__ dt, const float* __restrict__ xc,
                        const float* __restrict__ dbc, const float* __restrict__ A_log,
                        float* __restrict__ hloc, float* __restrict__ cdout)
{
    int warp = threadIdx.x >> 5;
    int wg   = (blockIdx.x<<3) + warp;
    int lane = threadIdx.x & 31;
    int s = lane & 15, half = lane >> 4;
    int dpair = wg & 63, chunk = (wg>>6) & 63, b = wg>>12;
    int d = (dpair<<1) + half;
    float Aval = -__expf(A_log[d*16+s]);
    float h = 0.f, cd = 0.f;
    size_t rowbase = (size_t)b*LL + (chunk<<8);
    const float* dtp = dt  + rowbase*128 + d;
    const float* xcp = xc  + rowbase*128 + d;
    const float* bp  = dbc + rowbase*36 + 4 + s;
#pragma unroll 8
    for (int t=0;t<CHKS;t++) {
        float dtv = dtp[t*128], xcv = xcp[t*128], Bv = bp[t*36];
        h = fmaf(h, __expf(dtv*Aval), dtv*xcv*Bv);
        cd += dtv;
    }
    int cidx = (b*128+d)*NCHK + chunk;
    hloc[cidx*16+s] = h;
    if (s == 0 ) cdout[cidx] = cd;
}

__global__ void carry_k(const float* __restrict__ hloc, const float* __restrict__ cd,
                        const float* __restrict__ A_log, float* __restrict__ Hst)
{
    int idx = blockIdx.x*256 + threadIdx.x;
    if (idx >= BB*DI*DS) return;
    int s = idx & 15, d = (idx>>4)&127, b = idx>>11;
    float Aval = -__expf(A_log[d*16+s]);
    float H = 0.f;
    int base = (b*128+d)*NCHK;
    for (int c=0;c<NCHK;c++) {
        Hst[(base+c)*16+s] = H;
        H = fmaf(H, __expf(Aval*cd[base+c]), hloc[(base+c)*16+s]);
    }
}

__global__ void scan2_k(const float* __restrict__ dt, const float* __restrict__ xc,
                        const float* __restrict__ dbc, const float* __restrict__ A_log,
                        const float* __restrict__ Hst, const float* __restrict__ xz,
                        const float* __restrict__ Dvec, float* __restrict__ ygt)
{
    __shared__ float shy[8][2][CHKS];
    int warp = threadIdx.x >> 5;
    int wg   = (blockIdx.x<<3) + warp;
    int lane = threadIdx.x & 31;
    int s = lane & 15, half = lane >> 4;
    int dpair = wg & 63, chunk = (wg>>6) & 63, b = wg>>12;
    int d = (dpair<<1) + half;
    float Aval = -__expf(A_log[d*16+s]);
    float h = Hst[((b*128+d)*NCHK + chunk)*16 + s];
    float Dv = Dvec[d];
    int t0 = chunk<<8;
    size_t rowbase = (size_t)b*LL + t0;
    const float* dtp = dt  + rowbase*128 + d;
    const float* xcp = xc  + rowbase*128 + d;
    const float* bp  = dbc + rowbase*36 + 4 + s;
    const float* cp  = dbc + rowbase*36 + 20 + s;
    const float* zp  = xz  + rowbase*256 + 128 + d;
#pragma unroll 4
    for (int t=0;t<CHKS;t++) {
        float dtv = dtp[t*128], xcv = xcp[t*128], Bv = bp[t*36], Cv = cp[t*36];
        h = fmaf(h, __expf(dtv*Aval), dtv*xcv*Bv);
        float p = h*Cv;
        p += __shfl_xor_sync(0xffffffffu, p, 1);
        p += __shfl_xor_sync(0xffffffffu, p, 2);
        p += __shfl_xor_sync(0xffffffffu, p, 4);
        p += __shfl_xor_sync(0xffffffffu, p, 8);
        if (s == 0) {
            float zv = zp[(size_t)t*256];
            float y = fmaf(xcv, Dv, p);
            float sig = 1.f/(1.f+__expf(-zv));
            shy[warp][half][t] = y*zv*sig;
        }
    }
    __syncwarp();
#pragma unroll
    for (int r=0;r<2;r++) {
        int dd = (dpair<<1) + r;
        float* dst = ygt + ((size_t)b*128 + dd)*LL + t0;
        for (int t=lane;t<CHKS;t+=32) dst[t] = shy[warp][r][t];
    }
}

__global__ void mag_k(const float* __restrict__ re, const float* __restrict__ im,
                      float* __restrict__ mg)
{
    int i = blockIdx.x*256 + threadIdx.x;
    if (i >= NIMG*FPIX) return;
    float r = re[i], m = im[i];
    mg[i] = sqrtf(r*r + m*m);
}

__global__ void phase_k(const float* __restrict__ re, const float* __restrict__ im,
                        const float* __restrict__ mg, const float* __restrict__ M2,
                        float* __restrict__ Zr, float* __restrict__ Zi)
{
    int i = blockIdx.x*256 + threadIdx.x;
    if (i >= NIMG*FPIX) return;
    float m = mg[i], m2 = M2[i];
    if (m > 1e-20f) {
        float sc = m2/m;
        Zr[i] = re[i]*sc; Zi[i] = im[i]*sc;
    } else { Zr[i] = m2; Zi[i] = 0.f; }
}

static void G(const float* A, const float* A2, int lam, int lak, int sA,
              const float* B, const float* B2, int lbk, int lbn, int sB,
              float* C, int ldc, int sC, int M, int N, int K, int batch,
              const float* bias, int bm, int relu)
{
    dim3 grid((N+63)>>6, (M+63)>>6, batch);
    if (A2) sgemm<true ><<<grid,256>>>(A,A2,lam,lak,sA,B,B2,lbk,lbn,sB,C,ldc,sC,M,N,K,bias,bm,relu);
    else    sgemm<false><<<grid,256>>>(A,nullptr,lam,lak,sA,B,nullptr,lbk,lbn,sB,C,ldc,sC,M,N,K,bias,bm,relu);
}

extern "C" void kernel_launch(void* const* d_in, const int* in_sizes, int n_in,
                              void* d_out, int out_size)
{
    const float* x      = (const float*)d_in[0];
    const float* W_in   = (const float*)d_in[1];
    const float* conv_w = (const float*)d_in[2];
    const float* conv_b = (const float*)d_in[3];
    const float* W_xproj= (const float*)d_in[4];
    const float* W_dt   = (const float*)d_in[5];
    const float* b_dt   = (const float*)d_in[6];
    const float* A_log  = (const float*)d_in[7];
    const float* Dvec   = (const float*)d_in[8];
    const float* W_out  = (const float*)d_in[9];
    const float* Wf1    = (const float*)d_in[10];
    const float* bf1    = (const float*)d_in[11];
    const float* Wf2    = (const float*)d_in[12];
    const float* bf2    = (const float*)d_in[13];
    const float* W_enh  = (const float*)d_in[14];
    const float* b_enh  = (const float*)d_in[15];
    const float* W_seg  = (const float*)d_in[16];
    const float* b_seg  = (const float*)d_in[17];
    float* out = (float*)d_out;

    void* pv;
    cudaGetSymbolAddress(&pv, d_xz);   float* p_xz  = (float*)pv;
    cudaGetSymbolAddress(&pv, d_xc);   float* p_xc  = (float*)pv;
    cudaGetSymbolAddress(&pv, d_dbc);  float* p_dbc = (float*)pv;
    cudaGetSymbolAddress(&pv, d_dt);   float* p_dt  = (float*)pv;
    cudaGetSymbolAddress(&pv, d_hloc); float* p_hl  = (float*)pv;
    cudaGetSymbolAddress(&pv, d_cd);   float* p_cd  = (float*)pv;
    cudaGetSymbolAddress(&pv, d_Hst);  float* p_Hs  = (float*)pv;
    cudaGetSymbolAddress(&pv, d_ygt);  float* p_yg  = (float*)pv;
    cudaGetSymbolAddress(&pv, d_xsp);  float* p_xsp = (float*)pv;
    cudaGetSymbolAddress(&pv, d_RT);   float* p_RT  = (float*)pv;
    cudaGetSymbolAddress(&pv, d_Cre);  float* p_Cre = (float*)pv;
    cudaGetSymbolAddress(&pv, d_Cim);  float* p_Cim = (float*)pv;
    cudaGetSymbolAddress(&pv, d_mag);  float* p_mag = (float*)pv;
    cudaGetSymbolAddress(&pv, d_M1);   float* p_M1  = (float*)pv;
    cudaGetSymbolAddress(&pv, d_M2);   float* p_M2  = (float*)pv;
    cudaGetSymbolAddress(&pv, d_Zr);   float* p_Zr  = (float*)pv;
    cudaGetSymbolAddress(&pv, d_Zi);   float* p_Zi  = (float*)pv;
    cudaGetSymbolAddress(&pv, d_Yr);   float* p_Yr  = (float*)pv;
    cudaGetSymbolAddress(&pv, d_Yi);   float* p_Yi  = (float*)pv;
    cudaGetSymbolAddress(&pv, d_xfr);  float* p_xfr = (float*)pv;
    cudaGetSymbolAddress(&pv, d_TW1);  float* p_TW1 = (float*)pv;
    cudaGetSymbolAddress(&pv, d_TCOS); float* p_TC  = (float*)pv;
    cudaGetSymbolAddress(&pv, d_TSIN); float* p_TS  = (float*)pv;
    cudaGetSymbolAddress(&pv, d_TSINN);float* p_TSN = (float*)pv;
    cudaGetSymbolAddress(&pv, d_IRW1); float* p_I1  = (float*)pv;
    cudaGetSymbolAddress(&pv, d_IRW2); float* p_I2  = (float*)pv;

    gen_tables<<<65, 256>>>();

    // ---- Mamba branch ----
    // xz[b] (L x 256) = xf[b] (L x 64) @ W_in ; xf[m,k] = x[b, k*L + m]
    G(x,0, 1, LL, CC*LL,  W_in,0, 256,1, 0,  p_xz, 256, LL*256,  LL, 256, CC, BB, 0,0,0);
    conv_silu_k<<<(BL*DI+255)/256,256>>>(p_xz, conv_w, conv_b, p_xc);
    // dbc (BL x 36) = xc (BL x 128) @ W_xproj
    G(p_xc,0, 128,1,0,  W_xproj,0, 36,1,0,  p_dbc, 36,0,  BL, 36, 128, 1, 0,0,0);
    dt_proj_k<<<(BL*DI+255)/256,256>>>(p_dbc, W_dt, b_dt, p_dt);
    scan1_k<<<2048,256>>>(p_dt, p_xc, p_dbc, A_log, p_hl, p_cd);
    carry_k<<<32,256>>>(p_hl, p_cd, A_log, p_Hs);
    scan2_k<<<2048,256>>>(p_dt, p_xc, p_dbc, A_log, p_Hs, p_xz, Dvec, p_yg);
    // x_spatial channel-major: xsp[b](64 x L) = W_out^T (64x128) @ ygt[b](128 x L)
    G(W_out,0, 1, CC, 0,  p_yg,0, LL,1, DI*LL,  p_xsp, LL, CC*LL,  CC, LL, DI, BB, 0,0,0);

    // ---- Frequency branch (DFT GEMMs) ----
    // row rfft: RT (32768 x 128) = x (32768 x 128) @ TW1[:, :128]; cols 128-129 via tail kernel
    G(x,0, 128,1,0,  p_TW1,0, 130,1,0,  p_RT, 130,0,  32768, 128, 128, 1, 0,0,0);
    rfft_tail_k<<<8192,256>>>(x, p_RT);
    // column FFT per image (N=64 main; Nyquist col 64 via nyq_k)
    G(p_TC, p_TS,  128,1,0,  p_RT, p_RT+65, 130,1, 128*130,  p_Cre, NKF, FPIX,  128, 64, 128, NIMG, 0,0,0);
    G(p_TC, p_TSN, 128,1,0,  p_RT+65, p_RT, 130,1, 128*130,  p_Cim, NKF, FPIX,  128, 64, 128, NIMG, 0,0,0);
    nyq_k<<<4096,256>>>(p_TC, p_TS,  p_RT+64,  p_RT+129, 130, 128*130, p_Cre, FPIX);
    nyq_k<<<4096,256>>>(p_TC, p_TSN, p_RT+129, p_RT+64,  130, 128*130, p_Cim, FPIX);
    mag_k<<<(NIMG*FPIX+255)/256,256>>>(p_Cre, p_Cim, p_mag);
    // channel mix per batch: M1 = relu(Wf1 @ mag + bf1); M2 = Wf2 @ M1 + bf2
    G(Wf1,0, CC,1,0,  p_mag,0, FPIX,1, CC*FPIX,  p_M1, FPIX, CC*FPIX,  CC, FPIX, CC, BB, bf1, 2, 1);
    G(Wf2,0, CC,1,0,  p_M1,0,  FPIX,1, CC*FPIX,  p_M2, FPIX, CC*FPIX,  CC, FPIX, CC, BB, bf2, 2, 0);
    phase_k<<<(NIMG*FPIX+255)/256,256>>>(p_Cre, p_Cim, p_mag, p_M2, p_Zr, p_Zi);
    // inverse column FFT (N=64 main; Nyquist col via nyq_k)
    G(p_TC, p_TSN, 128,1,0,  p_Zr, p_Zi, NKF,1, FPIX,  p_Yr, NKF, FPIX,  128, 64, 128, NIMG, 0,0,0);
    G(p_TS, p_TC,  128,1,0,  p_Zr, p_Zi, NKF,1, FPIX,  p_Yi, NKF, FPIX,  128, 64, 128, NIMG, 0,0,0);
    nyq_k<<<4096,256>>>(p_TC, p_TSN, p_Zr+64, p_Zi+64, NKF, FPIX, p_Yr, FPIX);
    nyq_k<<<4096,256>>>(p_TS, p_TC,  p_Zr+64, p_Zi+64, NKF, FPIX, p_Yi, FPIX);
    // irfft rows + fused residual add of x_spatial:
    // xfr = Yr@IRW1 + Yi@IRW2 + xsp   (per image, M=128 h, N=128 w, K=65)
    G(p_Yr, p_Yi, NKF,1, FPIX,  p_I1, p_I2, 128,1, 0,  p_xfr, 128, LL,  128, 128, NKF, NIMG, p_xsp, 3, 0);

    // ---- Heads (read fused directly) ----
    G(W_enh,0, CC,1,0,  p_xfr,0, LL,1, CC*LL,  out,            LL, CC*LL,  CC, LL, CC, BB, b_enh, 2, 0);
    G(W_seg,0, CC,1,0,  p_xfr,0, LL,1, CC*LL,  out + BB*CC*LL, LL, CC*LL,  CC, LL, CC, BB, b_seg, 2, 0);
}

// round 15
// speedup vs baseline: 1.2112x; 1.0290x over previous
#include <cuda_runtime.h>
#include <math.h>

#define BB 4
#define CC 64
#define LL 16384
#define BL 65536
#define DI 128
#define DS 16
#define NKF 65
#define NIMG 256
#define NCHK 64
#define CHKS 256
#define FPIX (NKF*128)   // 8320 freq pixels per image

__device__ float d_xz [BL*256];
__device__ float d_xc [BL*DI];
__device__ float d_dbc[BL*36];
__device__ float d_dt [BL*DI];
__device__ float d_hloc[BB*DI*NCHK*DS];
__device__ float d_cd  [BB*DI*NCHK];
__device__ float d_Hst [BB*DI*NCHK*DS];
__device__ float d_ygt [BB*DI*LL];
__device__ float d_xsp [BB*CC*LL];
__device__ float d_RT  [32768*130];
__device__ float d_Cre [NIMG*FPIX];
__device__ float d_Cim [NIMG*FPIX];
__device__ float d_mag [NIMG*FPIX];
__device__ float d_M1  [NIMG*FPIX];
__device__ float d_M2  [NIMG*FPIX];
__device__ float d_Zr  [NIMG*FPIX];
__device__ float d_Zi  [NIMG*FPIX];
__device__ float d_Yr  [NIMG*FPIX];
__device__ float d_Yi  [NIMG*FPIX];
__device__ float d_xfr [BB*CC*LL];
__device__ float d_TW1 [128*130];
__device__ float d_TCOS[128*128];
__device__ float d_TSIN[128*128];
__device__ float d_TSINN[128*128];
__device__ float d_IRW1[NKF*128];
__device__ float d_IRW2[NKF*128];

__global__ void gen_tables() {
    int i = blockIdx.x*256 + threadIdx.x;
    if (i < 128*130) {
        int w = i/130, j = i%130;
        int k = (j < NKF) ? j : j-NKF;
        float s,c; sincospif((float)((w*k)&127)/64.0f, &s, &c);
        d_TW1[i] = (j < NKF) ? c : -s;
    }
    if (i < 128*128) {
        int u = i/128, h = i%128;
        float s,c; sincospif((float)((u*h)&127)/64.0f, &s, &c);
        d_TCOS[i]=c; d_TSIN[i]=s; d_TSINN[i]=-s;
    }
    if (i < NKF*128) {
        int kf = i/128, w = i%128;
        float a = (kf==0 || kf==64) ? 1.0f : 2.0f;
        float s,c; sincospif((float)((kf*w)&127)/64.0f, &s, &c);
        d_IRW1[i] =  a*c*(1.0f/16384.0f);
        d_IRW2[i] = -a*s*(1.0f/16384.0f);
    }
}

// C[m,n] = sum_k A[m,k]*B[k,n] (+ A2[m,k]*B2[k,n] if DUAL)
// biasMode: 0=none, 1=bias[n], 2=bias[m], 3=residual matrix add (bias has C layout)
template<bool DUAL>
__global__ void sgemm(const float* __restrict__ A, const float* __restrict__ A2,
                      int lda_m, int lda_k, int sA,
                      const float* __restrict__ B, const float* __restrict__ B2,
                      int ldb_k, int ldb_n, int sB,
                      float* __restrict__ C, int ldc, int sC,
                      int M, int N, int K,
                      const float* __restrict__ bias, int biasMode, int doRelu)
{
    __shared__ float As[16][68], Bs[16][68], As2[16][68], Bs2[16][68];
    int bz = blockIdx.z;
    const float* Ab  = A + (size_t)bz*sA;
    const float* Bb  = B + (size_t)bz*sB;
    const float* A2b = DUAL ? (A2 + (size_t)bz*sA) : A;
    const float* B2b = DUAL ? (B2 + (size_t)bz*sB) : B;
    float* Cb = C + (size_t)bz*sC;
    int m0 = blockIdx.y<<6, n0 = blockIdx.x<<6;
    int tid = threadIdx.x, tx = tid&15, ty = tid>>4;
    float acc[4][4];
#pragma unroll
    for (int i=0;i<4;i++)
#pragma unroll
        for (int j=0;j<4;j++) acc[i][j]=0.f;

    for (int k0 = 0; k0 < K; k0 += 16) {
        if (lda_k == 1) {
            int kl = tid&15, ml0 = tid>>4;
#pragma unroll
            for (int i=0;i<4;i++) {
                int ml = ml0 + (i<<4), m = m0+ml, k = k0+kl;
                bool ok = (m<M)&&(k<K);
                As[kl][ml] = ok ? Ab[(size_t)m*lda_m + k] : 0.f;
                if (DUAL) As2[kl][ml] = ok ? A2b[(size_t)m*lda_m + k] : 0.f;
            }
        } else {
            int ml = tid&63, kl0 = tid>>6;
#pragma unroll
            for (int i=0;i<4;i++) {
                int kl = kl0 + (i<<2), m = m0+ml, k = k0+kl;
                bool ok = (m<M)&&(k<K);
                As[kl][ml] = ok ? Ab[(size_t)m*lda_m + (size_t)k*lda_k] : 0.f;
                if (DUAL) As2[kl][ml] = ok ? A2b[(size_t)m*lda_m + (size_t)k*lda_k] : 0.f;
            }
        }
        if (ldb_n == 1) {
            int nl = tid&63, kl0 = tid>>6;
#pragma unroll
            for (int i=0;i<4;i++) {
                int kl = kl0 + (i<<2), n = n0+nl, k = k0+kl;
                bool ok = (k<K)&&(n<N);
                Bs[kl][nl] = ok ? Bb[(size_t)k*ldb_k + n] : 0.f;
                if (DUAL) Bs2[kl][nl] = ok ? B2b[(size_t)k*ldb_k + n] : 0.f;
            }
        } else {
            int kl = tid&15, nl0 = tid>>4;
#pragma unroll
            for (int i=0;i<4;i++) {
                int nl = nl0 + (i<<4), n = n0+nl, k = k0+kl;
                bool ok = (k<K)&&(n<N);
                Bs[kl][nl] = ok ? Bb[(size_t)k*ldb_k + (size_t)n*ldb_n] : 0.f;
                if (DUAL) Bs2[kl][nl] = ok ? B2b[(size_t)k*ldb_k + (size_t)n*ldb_n] : 0.f;
            }
        }
        __syncthreads();
#pragma unroll
        for (int kk=0; kk<16; kk++) {
            float4 av = *(const float4*)&As[kk][ty<<2];
            float4 bv = *(const float4*)&Bs[kk][tx<<2];
            float a[4]={av.x,av.y,av.z,av.w}, b[4]={bv.x,bv.y,bv.z,bv.w};
#pragma unroll
            for (int i=0;i<4;i++)
#pragma unroll
                for (int j=0;j<4;j++) acc[i][j] = fmaf(a[i], b[j], acc[i][j]);
            if (DUAL) {
                float4 av2 = *(const float4*)&As2[kk][ty<<2];
                float4 bv2 = *(const float4*)&Bs2[kk][tx<<2];
                float a2[4]={av2.x,av2.y,av2.z,av2.w}, b2[4]={bv2.x,bv2.y,bv2.z,bv2.w};
#pragma unroll
                for (int i=0;i<4;i++)
#pragma unroll
                    for (int j=0;j<4;j++) acc[i][j] = fmaf(a2[i], b2[j], acc[i][j]);
            }
        }
        __syncthreads();
    }
#pragma unroll
    for (int i=0;i<4;i++) {
        int m = m0 + (ty<<2) + i;
        if (m >= M) continue;
#pragma unroll
        for (int j=0;j<4;j++) {
            int n = n0 + (tx<<2) + j;
            if (n >= N) continue;
            float v = acc[i][j];
            if (biasMode == 1) v += bias[n];
            else if (biasMode == 2) v += bias[m];
            else if (biasMode == 3) v += bias[(size_t)bz*sC + (size_t)m*ldc + n];
            if (doRelu) v = fmaxf(v, 0.f);
            Cb[(size_t)m*ldc + n] = v;
        }
    }
}

// ---------------------------------------------------------------------------
// Complex GEMM: one pass computes both
//   Cr = Ac@Br + S1*As@Bi
//   Ci = Ac@Bi - S1*As@Br
// A: k-contiguous 128-wide tables (Ac=TCOS, As=TSIN). B: ldb_n==1, batched.
// Optionally writes mag = sqrt(Cr^2+Ci^2).
// ---------------------------------------------------------------------------
template<int S1, bool WMAG>
__global__ void __launch_bounds__(256)
cgemm(const float* __restrict__ Ac, const float* __restrict__ Asn,
      const float* __restrict__ Br, const float* __restrict__ Bi, int ldbk, int sB,
      float* __restrict__ outR, float* __restrict__ outI, float* __restrict__ outM,
      int ldc, int sC, int M, int N, int K)
{
    __shared__ float Acs[16][68], Ass[16][68], Brs[16][68], Bis[16][68];
    int bz = blockIdx.z;
    const float* BrB = Br + (size_t)bz*sB;
    const float* BiB = Bi + (size_t)bz*sB;
    int m0 = blockIdx.y<<6, n0 = blockIdx.x<<6;
    int tid = threadIdx.x, tx = tid&15, ty = tid>>4;
    float aR[4][4], aI[4][4];
#pragma unroll
    for (int i=0;i<4;i++)
#pragma unroll
        for (int j=0;j<4;j++) { aR[i][j]=0.f; aI[i][j]=0.f; }

    for (int k0 = 0; k0 < K; k0 += 16) {
        {   // A tiles (lda_k == 1, lda_m = 128)
            int kl = tid&15, ml0 = tid>>4;
#pragma unroll
            for (int i=0;i<4;i++) {
                int ml = ml0 + (i<<4), m = m0+ml, k = k0+kl;
                bool ok = (m<M);
                Acs[kl][ml] = ok ? Ac [(size_t)m*128 + k] : 0.f;
                Ass[kl][ml] = ok ? Asn[(size_t)m*128 + k] : 0.f;
            }
        }
        {   // B tiles (ldb_n == 1)
            int nl = tid&63, kl0 = tid>>6;
#pragma unroll
            for (int i=0;i<4;i++) {
                int kl = kl0 + (i<<2), n = n0+nl, k = k0+kl;
                bool ok = (n<N);
                Brs[kl][nl] = ok ? BrB[(size_t)k*ldbk + n] : 0.f;
                Bis[kl][nl] = ok ? BiB[(size_t)k*ldbk + n] : 0.f;
            }
        }
        __syncthreads();
#pragma unroll
        for (int kk=0; kk<16; kk++) {
            float4 acv = *(const float4*)&Acs[kk][ty<<2];
            float4 asv = *(const float4*)&Ass[kk][ty<<2];
            float4 brv = *(const float4*)&Brs[kk][tx<<2];
            float4 biv = *(const float4*)&Bis[kk][tx<<2];
            float ac[4]={acv.x,acv.y,acv.z,acv.w};
            float as[4]={asv.x,asv.y,asv.z,asv.w};
            float br[4]={brv.x,brv.y,brv.z,brv.w};
            float bi[4]={biv.x,biv.y,biv.z,biv.w};
            float sbi[4], sbr[4];
#pragma unroll
            for (int j=0;j<4;j++) {
                sbi[j] = (S1>0) ? bi[j] : -bi[j];   //  S1*bi
                sbr[j] = (S1>0) ? -br[j] : br[j];   // -S1*br
            }
#pragma unroll
            for (int i=0;i<4;i++)
#pragma unroll
                for (int j=0;j<4;j++) {
                    aR[i][j] = fmaf(as[i], sbi[j], fmaf(ac[i], br[j], aR[i][j]));
                    aI[i][j] = fmaf(as[i], sbr[j], fmaf(ac[i], bi[j], aI[i][j]));
                }
        }
        __syncthreads();
    }
    float* oR = outR + (size_t)bz*sC;
    float* oI = outI + (size_t)bz*sC;
    float* oM = WMAG ? (outM + (size_t)bz*sC) : outR;
#pragma unroll
    for (int i=0;i<4;i++) {
        int m = m0 + (ty<<2) + i;
        if (m >= M) continue;
#pragma unroll
        for (int j=0;j<4;j++) {
            int n = n0 + (tx<<2) + j;
            if (n >= N) continue;
            float r = aR[i][j], im = aI[i][j];
            oR[(size_t)m*ldc + n] = r;
            oI[(size_t)m*ldc + n] = im;
            if (WMAG) oM[(size_t)m*ldc + n] = sqrtf(r*r + im*im);
        }
    }
}

// Complex Nyquist column (kf=64): warp per output u; writes re, im (+mag).
template<int S1, bool WMAG>
__global__ void cnyq_k(const float* __restrict__ Ac, const float* __restrict__ Asn,
                       const float* __restrict__ Br, const float* __restrict__ Bi,
                       int ldb, int sB,
                       float* __restrict__ outR, float* __restrict__ outI,
                       float* __restrict__ outM, int sC)
{
    int w = (blockIdx.x*256 + threadIdx.x) >> 5;   // 32768 outputs
    int lane = threadIdx.x & 31;
    int img = w >> 7, u = w & 127;
    const float* br = Br + (size_t)img*sB;
    const float* bi = Bi + (size_t)img*sB;
    float sr = 0.f, si = 0.f;
#pragma unroll
    for (int kk=0; kk<4; kk++) {
        int k = lane + kk*32;
        float ac = Ac[u*128+k], as = Asn[u*128+k];
        float vr = br[(size_t)k*ldb], vi = bi[(size_t)k*ldb];
        sr += ac*vr + ((S1>0) ? as*vi : -as*vi);
        si += ac*vi - ((S1>0) ? as*vr : -as*vr);
    }
#pragma unroll
    for (int o=16; o>=1; o>>=1) {
        sr += __shfl_xor_sync(0xffffffffu, sr, o);
        si += __shfl_xor_sync(0xffffffffu, si, o);
    }
    if (lane == 0) {
        size_t idx = (size_t)img*sC + u*65 + 64;
        outR[idx] = sr;
        outI[idx] = si;
        if (WMAG) outM[idx] = sqrtf(sr*sr + si*si);
    }
}

// rfft columns 128,129 of the 130-wide row transform, warp-per-output.
__global__ void rfft_tail_k(const float* __restrict__ x, float* __restrict__ RT)
{
    int w = (blockIdx.x*256 + threadIdx.x) >> 5;   // 65536 outputs
    int lane = threadIdx.x & 31;
    int row = w >> 1, j = 128 + (w & 1);
    const float* xr = x + (size_t)row*128;
    float s = 0.f;
#pragma unroll
    for (int kk=0; kk<4; kk++) {
        int k = lane + kk*32;
        s += xr[k]*d_TW1[k*130+j];
    }
#pragma unroll
    for (int o=16; o>=1; o>>=1) s += __shfl_xor_sync(0xffffffffu, s, o);
    if (lane == 0) RT[(size_t)row*130 + j] = s;
}

__global__ void conv_silu_k(const float* __restrict__ xz, const float* __restrict__ cw,
                            const float* __restrict__ cb, float* __restrict__ xc)
{
    int idx = blockIdx.x*256 + threadIdx.x;
    if (idx >= BL*DI) return;
    int d = idx & 127, bl = idx >> 7, l = bl & (LL-1);
    size_t base = (size_t)bl*256 + d;
    float acc = cb[d];
#pragma unroll
    for (int k=0;k<4;k++) {
        int lsrc = l - 3 + k;
        float v = (lsrc >= 0) ? xz[base + (size_t)(k-3)*256] : 0.f;
        acc = fmaf(cw[d*4+k], v, acc);
    }
    float sig = 1.f/(1.f+__expf(-acc));
    xc[idx] = acc*sig;
}

__global__ void dt_proj_k(const float* __restrict__ dbc, const float* __restrict__ Wdt,
                          const float* __restrict__ bdt, float* __restrict__ dt)
{
    int idx = blockIdx.x*256 + threadIdx.x;
    if (idx >= BL*DI) return;
    int d = idx & 127, bl = idx >> 7;
    const float* row = dbc + (size_t)bl*36;
    float s = bdt[d];
#pragma unroll
    for (int r=0;r<4;r++) s = fmaf(row[r], Wdt[r*128+d], s);
    dt[idx] = (s > 20.f) ? s : log1pf(__expf(s));
}

__global__ void scan1_k(const float* __restrict__ dt, const float* __restrict__ xc,
                        const float* __restrict__ dbc, const float* __restrict__ A_log,
                        float* __restrict__ hloc, float* __restrict__ cdout)
{
    int warp = threadIdx.x >> 5;
    int wg   = (blockIdx.x<<3) + warp;
    int lane = threadIdx.x & 31;
    int s = lane & 15, half = lane >> 4;
    int dpair = wg & 63, chunk = (wg>>6) & 63, b = wg>>12;
    int d = (dpair<<1) + half;
    float Aval = -__expf(A_log[d*16+s]);
    float h = 0.f, cd = 0.f;
    size_t rowbase = (size_t)b*LL + (chunk<<8);
    const float* dtp = dt  + rowbase*128 + d;
    const float* xcp = xc  + rowbase*128 + d;
    const float* bp  = dbc + rowbase*36 + 4 + s;
#pragma unroll 8
    for (int t=0;t<CHKS;t++) {
        float dtv = dtp[t*128], xcv = xcp[t*128], Bv = bp[t*36];
        h = fmaf(h, __expf(dtv*Aval), dtv*xcv*Bv);
        cd += dtv;
    }
    int cidx = (b*128+d)*NCHK + chunk;
    hloc[cidx*16+s] = h;
    if (s == 0 ) cdout[cidx] = cd;
}

__global__ void carry_k(const float* __restrict__ hloc, const float* __restrict__ cd,
                        const float* __restrict__ A_log, float* __restrict__ Hst)
{
    int idx = blockIdx.x*256 + threadIdx.x;
    if (idx >= BB*DI*DS) return;
    int s = idx & 15, d = (idx>>4)&127, b = idx>>11;
    float Aval = -__expf(A_log[d*16+s]);
    float H = 0.f;
    int base = (b*128+d)*NCHK;
    for (int c=0;c<NCHK;c++) {
        Hst[(base+c)*16+s] = H;
        H = fmaf(H, __expf(Aval*cd[base+c]), hloc[(base+c)*16+s]);
    }
}

__global__ void scan2_k(const float* __restrict__ dt, const float* __restrict__ xc,
                        const float* __restrict__ dbc, const float* __restrict__ A_log,
                        const float* __restrict__ Hst, const float* __restrict__ xz,
                        const float* __restrict__ Dvec, float* __restrict__ ygt)
{
    __shared__ float shy[8][2][CHKS];
    int warp = threadIdx.x >> 5;
    int wg   = (blockIdx.x<<3) + warp;
    int lane = threadIdx.x & 31;
    int s = lane & 15, half = lane >> 4;
    int dpair = wg & 63, chunk = (wg>>6) & 63, b = wg>>12;
    int d = (dpair<<1) + half;
    float Aval = -__expf(A_log[d*16+s]);
    float h = Hst[((b*128+d)*NCHK + chunk)*16 + s];
    float Dv = Dvec[d];
    int t0 = chunk<<8;
    size_t rowbase = (size_t)b*LL + t0;
    const float* dtp = dt  + rowbase*128 + d;
    const float* xcp = xc  + rowbase*128 + d;
    const float* bp  = dbc + rowbase*36 + 4 + s;
    const float* cp  = dbc + rowbase*36 + 20 + s;
    const float* zp  = xz  + rowbase*256 + 128 + d;
#pragma unroll 4
    for (int t=0;t<CHKS;t++) {
        float dtv = dtp[t*128], xcv = xcp[t*128], Bv = bp[t*36], Cv = cp[t*36];
        h = fmaf(h, __expf(dtv*Aval), dtv*xcv*Bv);
        float p = h*Cv;
        p += __shfl_xor_sync(0xffffffffu, p, 1);
        p += __shfl_xor_sync(0xffffffffu, p, 2);
        p += __shfl_xor_sync(0xffffffffu, p, 4);
        p += __shfl_xor_sync(0xffffffffu, p, 8);
        if (s == 0) {
            float zv = zp[(size_t)t*256];
            float y = fmaf(xcv, Dv, p);
            float sig = 1.f/(1.f+__expf(-zv));
            shy[warp][half][t] = y*zv*sig;
        }
    }
    __syncwarp();
#pragma unroll
    for (int r=0;r<2;r++) {
        int dd = (dpair<<1) + r;
        float* dst = ygt + ((size_t)b*128 + dd)*LL + t0;
        for (int t=lane;t<CHKS;t+=32) dst[t] = shy[warp][r][t];
    }
}

__global__ void phase_k(const float* __restrict__ re, const float* __restrict__ im,
                        const float* __restrict__ mg, const float* __restrict__ M2,
                        float* __restrict__ Zr, float* __restrict__ Zi)
{
    int i = blockIdx.x*256 + threadIdx.x;
    if (i >= NIMG*FPIX) return;
    float m = mg[i], m2 = M2[i];
    if (m > 1e-20f) {
        float sc = m2/m;
        Zr[i] = re[i]*sc; Zi[i] = im[i]*sc;
    } else { Zr[i] = m2; Zi[i] = 0.f; }
}

static void G(const float* A, const float* A2, int lam, int lak, int sA,
              const float* B, const float* B2, int lbk, int lbn, int sB,
              float* C, int ldc, int sC, int M, int N, int K, int batch,
              const float* bias, int bm, int relu)
{
    dim3 grid((N+63)>>6, (M+63)>>6, batch);
    if (A2) sgemm<true ><<<grid,256>>>(A,A2,lam,lak,sA,B,B2,lbk,lbn,sB,C,ldc,sC,M,N,K,bias,bm,relu);
    else    sgemm<false><<<grid,256>>>(A,nullptr,lam,lak,sA,B,nullptr,lbk,lbn,sB,C,ldc,sC,M,N,K,bias,bm,relu);
}

extern "C" void kernel_launch(void* const* d_in, const int* in_sizes, int n_in,
                              void* d_out, int out_size)
{
    const float* x      = (const float*)d_in[0];
    const float* W_in   = (const float*)d_in[1];
    const float* conv_w = (const float*)d_in[2];
    const float* conv_b = (const float*)d_in[3];
    const float* W_xproj= (const float*)d_in[4];
    const float* W_dt   = (const float*)d_in[5];
    const float* b_dt   = (const float*)d_in[6];
    const float* A_log  = (const float*)d_in[7];
    const float* Dvec   = (const float*)d_in[8];
    const float* W_out  = (const float*)d_in[9];
    const float* Wf1    = (const float*)d_in[10];
    const float* bf1    = (const float*)d_in[11];
    const float* Wf2    = (const float*)d_in[12];
    const float* bf2    = (const float*)d_in[13];
    const float* W_enh  = (const float*)d_in[14];
    const float* b_enh  = (const float*)d_in[15];
    const float* W_seg  = (const float*)d_in[16];
    const float* b_seg  = (const float*)d_in[17];
    float* out = (float*)d_out;

    void* pv;
    cudaGetSymbolAddress(&pv, d_xz);   float* p_xz  = (float*)pv;
    cudaGetSymbolAddress(&pv, d_xc);   float* p_xc  = (float*)pv;
    cudaGetSymbolAddress(&pv, d_dbc);  float* p_dbc = (float*)pv;
    cudaGetSymbolAddress(&pv, d_dt);   float* p_dt  = (float*)pv;
    cudaGetSymbolAddress(&pv, d_hloc); float* p_hl  = (float*)pv;
    cudaGetSymbolAddress(&pv, d_cd);   float* p_cd  = (float*)pv;
    cudaGetSymbolAddress(&pv, d_Hst);  float* p_Hs  = (float*)pv;
    cudaGetSymbolAddress(&pv, d_ygt);  float* p_yg  = (float*)pv;
    cudaGetSymbolAddress(&pv, d_xsp);  float* p_xsp = (float*)pv;
    cudaGetSymbolAddress(&pv, d_RT);   float* p_RT  = (float*)pv;
    cudaGetSymbolAddress(&pv, d_Cre);  float* p_Cre = (float*)pv;
    cudaGetSymbolAddress(&pv, d_Cim);  float* p_Cim = (float*)pv;
    cudaGetSymbolAddress(&pv, d_mag);  float* p_mag = (float*)pv;
    cudaGetSymbolAddress(&pv, d_M1);   float* p_M1  = (float*)pv;
    cudaGetSymbolAddress(&pv, d_M2);   float* p_M2  = (float*)pv;
    cudaGetSymbolAddress(&pv, d_Zr);   float* p_Zr  = (float*)pv;
    cudaGetSymbolAddress(&pv, d_Zi);   float* p_Zi  = (float*)pv;
    cudaGetSymbolAddress(&pv, d_Yr);   float* p_Yr  = (float*)pv;
    cudaGetSymbolAddress(&pv, d_Yi);   float* p_Yi  = (float*)pv;
    cudaGetSymbolAddress(&pv, d_xfr);  float* p_xfr = (float*)pv;
    cudaGetSymbolAddress(&pv, d_TW1);  float* p_TW1 = (float*)pv;
    cudaGetSymbolAddress(&pv, d_TCOS); float* p_TC  = (float*)pv;
    cudaGetSymbolAddress(&pv, d_TSIN); float* p_TS  = (float*)pv;
    cudaGetSymbolAddress(&pv, d_TSINN);float* p_TSN = (float*)pv;
    cudaGetSymbolAddress(&pv, d_IRW1); float* p_I1  = (float*)pv;
    cudaGetSymbolAddress(&pv, d_IRW2); float* p_I2  = (float*)pv;

    gen_tables<<<65, 256>>>();

    // ---- Mamba branch ----
    // xz[b] (L x 256) = xf[b] (L x 64) @ W_in ; xf[m,k] = x[b, k*L + m]
    G(x,0, 1, LL, CC*LL,  W_in,0, 256,1, 0,  p_xz, 256, LL*256,  LL, 256, CC, BB, 0,0,0);
    conv_silu_k<<<(BL*DI+255)/256,256>>>(p_xz, conv_w, conv_b, p_xc);
    // dbc (BL x 36) = xc (BL x 128) @ W_xproj
    G(p_xc,0, 128,1,0,  W_xproj,0, 36,1,0,  p_dbc, 36,0,  BL, 36, 128, 1, 0,0,0);
    dt_proj_k<<<(BL*DI+255)/256,256>>>(p_dbc, W_dt, b_dt, p_dt);
    scan1_k<<<2048,256>>>(p_dt, p_xc, p_dbc, A_log, p_hl, p_cd);
    carry_k<<<32,256>>>(p_hl, p_cd, A_log, p_Hs);
    scan2_k<<<2048,256>>>(p_dt, p_xc, p_dbc, A_log, p_Hs, p_xz, Dvec, p_yg);
    // x_spatial channel-major: xsp[b](64 x L) = W_out^T (64x128) @ ygt[b](128 x L)
    G(W_out,0, 1, CC, 0,  p_yg,0, LL,1, DI*LL,  p_xsp, LL, CC*LL,  CC, LL, DI, BB, 0,0,0);

    // ---- Frequency branch ----
    // row rfft: RT (32768 x 128) = x (32768 x 128) @ TW1[:, :128]; cols 128-129 via tail kernel
    G(x,0, 128,1,0,  p_TW1,0, 130,1,0,  p_RT, 130,0,  32768, 128, 128, 1, 0,0,0);
    rfft_tail_k<<<8192,256>>>(x, p_RT);
    // column FFT per image: ONE complex GEMM (re+im+mag) over cols 0-63, cnyq for col 64.
    // Cre = TC@Rr + TS@Ri ; Cim = TC@Ri - TS@Rr   (S1 = +1)
    {
        dim3 grid(1, 2, NIMG);
        cgemm<1,true><<<grid,256>>>(p_TC, p_TS, p_RT, p_RT+65, 130, 128*130,
                                    p_Cre, p_Cim, p_mag, NKF, FPIX, 128, 64, 128);
    }
    cnyq_k<1,true><<<4096,256>>>(p_TC, p_TS, p_RT+64, p_RT+129, 130, 128*130,
                                 p_Cre, p_Cim, p_mag, FPIX);
    // channel mix per batch: M1 = relu(Wf1 @ mag + bf1); M2 = Wf2 @ M1 + bf2
    G(Wf1,0, CC,1,0,  p_mag,0, FPIX,1, CC*FPIX,  p_M1, FPIX, CC*FPIX,  CC, FPIX, CC, BB, bf1, 2, 1);
    G(Wf2,0, CC,1,0,  p_M1,0,  FPIX,1, CC*FPIX,  p_M2, FPIX, CC*FPIX,  CC, FPIX, CC, BB, bf2, 2, 0);
    phase_k<<<(NIMG*FPIX+255)/256,256>>>(p_Cre, p_Cim, p_mag, p_M2, p_Zr, p_Zi);
    // inverse column FFT: ONE complex GEMM. Yr = TC@Zr - TS@Zi ; Yi = TS@Zr + TC@Zi (S1 = -1)
    {
        dim3 grid(1, 2, NIMG);
        cgemm<-1,false><<<grid,256>>>(p_TC, p_TS, p_Zr, p_Zi, NKF, FPIX,
                                      p_Yr, p_Yi, nullptr, NKF, FPIX, 128, 64, 128);
    }
    cnyq_k<-1,false><<<4096,256>>>(p_TC, p_TS, p_Zr+64, p_Zi+64, NKF, FPIX,
                                   p_Yr, p_Yi, nullptr, FPIX);
    // irfft rows + fused residual add of x_spatial:
    // xfr = Yr@IRW1 + Yi@IRW2 + xsp   (per image, M=128 h, N=128 w, K=65)
    G(p_Yr, p_Yi, NKF,1, FPIX,  p_I1, p_I2, 128,1, 0,  p_xfr, 128, LL,  128, 128, NKF, NIMG, p_xsp, 3, 0);

    // ---- Heads (read fused directly) ----
    G(W_enh,0, CC,1,0,  p_xfr,0, LL,1, CC*LL,  out,            LL, CC*LL,  CC, LL, CC, BB, b_enh, 2, 0);
    G(W_seg,0, CC,1,0,  p_xfr,0, LL,1, CC*LL,  out + BB*CC*LL, LL, CC*LL,  CC, LL, CC, BB, b_seg, 2, 0);
}

// round 16
// speedup vs baseline: 1.2162x; 1.0041x over previous
#include <cuda_runtime.h>
#include <math.h>

#define BB 4
#define CC 64
#define LL 16384
#define BL 65536
#define DI 128
#define DS 16
#define NKF 65
#define NIMG 256
#define NCHK 64
#define CHKS 256
#define FPIX (NKF*128)   // 8320 freq pixels per image

__device__ float d_xz [BL*256];
__device__ float d_xc [BL*DI];
__device__ float d_dbc[BL*36];
__device__ float d_dt [BL*DI];
__device__ float d_hloc[BB*DI*NCHK*DS];
__device__ float d_cd  [BB*DI*NCHK];
__device__ float d_Hst [BB*DI*NCHK*DS];
__device__ float d_ygt [BB*DI*LL];
__device__ float d_xsp [BB*CC*LL];
__device__ float d_RT  [32768*130];
__device__ float d_Cre [NIMG*FPIX];
__device__ float d_Cim [NIMG*FPIX];
__device__ float d_mag [NIMG*FPIX];
__device__ float d_M1  [NIMG*FPIX];
__device__ float d_M2  [NIMG*FPIX];
__device__ float d_Zr  [NIMG*FPIX];
__device__ float d_Zi  [NIMG*FPIX];
__device__ float d_Yr  [NIMG*FPIX];
__device__ float d_Yi  [NIMG*FPIX];
__device__ float d_xfr [BB*CC*LL];
__device__ float d_TW1 [128*130];
__device__ float d_TCOS[128*128];
__device__ float d_TSIN[128*128];
__device__ float d_TSINN[128*128];
__device__ float d_IRW1[NKF*128];
__device__ float d_IRW2[NKF*128];

__global__ void gen_tables() {
    int i = blockIdx.x*256 + threadIdx.x;
    if (i < 128*130) {
        int w = i/130, j = i%130;
        int k = (j < NKF) ? j : j-NKF;
        float s,c; sincospif((float)((w*k)&127)/64.0f, &s, &c);
        d_TW1[i] = (j < NKF) ? c : -s;
    }
    if (i < 128*128) {
        int u = i/128, h = i%128;
        float s,c; sincospif((float)((u*h)&127)/64.0f, &s, &c);
        d_TCOS[i]=c; d_TSIN[i]=s; d_TSINN[i]=-s;
    }
    if (i < NKF*128) {
        int kf = i/128, w = i%128;
        float a = (kf==0 || kf==64) ? 1.0f : 2.0f;
        float s,c; sincospif((float)((kf*w)&127)/64.0f, &s, &c);
        d_IRW1[i] =  a*c*(1.0f/16384.0f);
        d_IRW2[i] = -a*s*(1.0f/16384.0f);
    }
}

// C[m,n] = sum_k A[m,k]*B[k,n] (+ A2[m,k]*B2[k,n] if DUAL)
// Block tile: (TM*16) x 64, microtile TM x 4 on 16x16 threads.
// biasMode: 0=none, 1=bias[n], 2=bias[m], 3=residual matrix add (bias has C layout)
template<bool DUAL, int TM>
__global__ void __launch_bounds__(256, 3)
sgemm(const float* __restrict__ A, const float* __restrict__ A2,
      int lda_m, int lda_k, int sA,
      const float* __restrict__ B, const float* __restrict__ B2,
      int ldb_k, int ldb_n, int sB,
      float* __restrict__ C, int ldc, int sC,
      int M, int N, int K,
      const float* __restrict__ bias, int biasMode, int doRelu)
{
    constexpr int BM = TM*16;
    __shared__ float As[16][BM+4], Bs[16][68];
    __shared__ float As2[DUAL?16:1][DUAL?(BM+4):1], Bs2[DUAL?16:1][DUAL?68:1];
    int bz = blockIdx.z;
    const float* Ab  = A + (size_t)bz*sA;
    const float* Bb  = B + (size_t)bz*sB;
    const float* A2b = DUAL ? (A2 + (size_t)bz*sA) : A;
    const float* B2b = DUAL ? (B2 + (size_t)bz*sB) : B;
    float* Cb = C + (size_t)bz*sC;
    int m0 = blockIdx.y*BM, n0 = blockIdx.x<<6;
    int tid = threadIdx.x, tx = tid&15, ty = tid>>4;
    float acc[TM][4];
#pragma unroll
    for (int i=0;i<TM;i++)
#pragma unroll
        for (int j=0;j<4;j++) acc[i][j]=0.f;

    for (int k0 = 0; k0 < K; k0 += 16) {
        if (lda_k == 1) {
            int kl = tid&15, ml0 = tid>>4;
#pragma unroll
            for (int i=0;i<TM;i++) {
                int ml = ml0 + (i<<4), m = m0+ml, k = k0+kl;
                bool ok = (m<M)&&(k<K);
                As[kl][ml] = ok ? Ab[(size_t)m*lda_m + k] : 0.f;
                if (DUAL) As2[kl][ml] = ok ? A2b[(size_t)m*lda_m + k] : 0.f;
            }
        } else {
#pragma unroll
            for (int i=0;i<TM;i++) {
                int idx = tid + i*256;
                int ml = idx % BM, kl = idx / BM;
                int m = m0+ml, k = k0+kl;
                bool ok = (m<M)&&(k<K);
                As[kl][ml] = ok ? Ab[(size_t)m*lda_m + (size_t)k*lda_k] : 0.f;
                if (DUAL) As2[kl][ml] = ok ? A2b[(size_t)m*lda_m + (size_t)k*lda_k] : 0.f;
            }
        }
        if (ldb_n == 1) {
            int nl = tid&63, kl0 = tid>>6;
#pragma unroll
            for (int i=0;i<4;i++) {
                int kl = kl0 + (i<<2), n = n0+nl, k = k0+kl;
                bool ok = (k<K)&&(n<N);
                Bs[kl][nl] = ok ? Bb[(size_t)k*ldb_k + n] : 0.f;
                if (DUAL) Bs2[kl][nl] = ok ? B2b[(size_t)k*ldb_k + n] : 0.f;
            }
        } else {
            int kl = tid&15, nl0 = tid>>4;
#pragma unroll
            for (int i=0;i<4;i++) {
                int nl = nl0 + (i<<4), n = n0+nl, k = k0+kl;
                bool ok = (k<K)&&(n<N);
                Bs[kl][nl] = ok ? Bb[(size_t)k*ldb_k + (size_t)n*ldb_n] : 0.f;
                if (DUAL) Bs2[kl][nl] = ok ? B2b[(size_t)k*ldb_k + (size_t)n*ldb_n] : 0.f;
            }
        }
        __syncthreads();
#pragma unroll
        for (int kk=0; kk<16; kk++) {
            float a[TM], b[4];
#pragma unroll
            for (int i=0;i<TM;i+=4) *(float4*)&a[i] = *(const float4*)&As[kk][ty*TM+i];
            *(float4*)&b[0] = *(const float4*)&Bs[kk][tx<<2];
#pragma unroll
            for (int i=0;i<TM;i++)
#pragma unroll
                for (int j=0;j<4;j++) acc[i][j] = fmaf(a[i], b[j], acc[i][j]);
            if (DUAL) {
                float a2[TM], b2[4];
#pragma unroll
                for (int i=0;i<TM;i+=4) *(float4*)&a2[i] = *(const float4*)&As2[kk][ty*TM+i];
                *(float4*)&b2[0] = *(const float4*)&Bs2[kk][tx<<2];
#pragma unroll
                for (int i=0;i<TM;i++)
#pragma unroll
                    for (int j=0;j<4;j++) acc[i][j] = fmaf(a2[i], b2[j], acc[i][j]);
            }
        }
        __syncthreads();
    }
#pragma unroll
    for (int i=0;i<TM;i++) {
        int m = m0 + ty*TM + i;
        if (m >= M) continue;
#pragma unroll
        for (int j=0;j<4;j++) {
            int n = n0 + (tx<<2) + j;
            if (n >= N) continue;
            float v = acc[i][j];
            if (biasMode == 1) v += bias[n];
            else if (biasMode == 2) v += bias[m];
            else if (biasMode == 3) v += bias[(size_t)bz*sC + (size_t)m*ldc + n];
            if (doRelu) v = fmaxf(v, 0.f);
            Cb[(size_t)m*ldc + n] = v;
        }
    }
}

// Two-head GEMM: C1 = A1@B + b1, C2 = A2@B + b2 sharing B tiles.
// A row-major [64x64], B k-major [64 x LL] per batch, bias per-row (m).
__global__ void __launch_bounds__(256, 3)
head2_k(const float* __restrict__ A1, const float* __restrict__ A2,
        const float* __restrict__ B, int sB,
        const float* __restrict__ b1, const float* __restrict__ b2,
        float* __restrict__ C1, float* __restrict__ C2, int sC)
{
    __shared__ float As1[16][68], As2[16][68], Bs[16][68];
    int bz = blockIdx.z;
    const float* Bb = B + (size_t)bz*sB;
    int n0 = blockIdx.x<<6;
    int tid = threadIdx.x, tx = tid&15, ty = tid>>4;
    float ac1[4][4], ac2[4][4];
#pragma unroll
    for (int i=0;i<4;i++)
#pragma unroll
        for (int j=0;j<4;j++) { ac1[i][j]=0.f; ac2[i][j]=0.f; }

    for (int k0 = 0; k0 < CC; k0 += 16) {
        {
            int kl = tid&15, ml0 = tid>>4;
#pragma unroll
            for (int i=0;i<4;i++) {
                int ml = ml0 + (i<<4), k = k0+kl;
                As1[kl][ml] = A1[(size_t)ml*CC + k];
                As2[kl][ml] = A2[(size_t)ml*CC + k];
            }
        }
        {
            int nl = tid&63, kl0 = tid>>6;
#pragma unroll
            for (int i=0;i<4;i++) {
                int kl = kl0 + (i<<2), n = n0+nl, k = k0+kl;
                Bs[kl][nl] = Bb[(size_t)k*LL + n];
            }
        }
        __syncthreads();
#pragma unroll
        for (int kk=0; kk<16; kk++) {
            float4 a1v = *(const float4*)&As1[kk][ty<<2];
            float4 a2v = *(const float4*)&As2[kk][ty<<2];
            float4 bv  = *(const float4*)&Bs[kk][tx<<2];
            float a1[4]={a1v.x,a1v.y,a1v.z,a1v.w};
            float a2[4]={a2v.x,a2v.y,a2v.z,a2v.w};
            float b[4]={bv.x,bv.y,bv.z,bv.w};
#pragma unroll
            for (int i=0;i<4;i++)
#pragma unroll
                for (int j=0;j<4;j++) {
                    ac1[i][j] = fmaf(a1[i], b[j], ac1[i][j]);
                    ac2[i][j] = fmaf(a2[i], b[j], ac2[i][j]);
                }
        }
        __syncthreads();
    }
    float* o1 = C1 + (size_t)bz*sC;
    float* o2 = C2 + (size_t)bz*sC;
#pragma unroll
    for (int i=0;i<4;i++) {
        int m = (ty<<2) + i;
        float bb1 = b1[m], bb2 = b2[m];
#pragma unroll
        for (int j=0;j<4;j++) {
            int n = n0 + (tx<<2) + j;
            o1[(size_t)m*LL + n] = ac1[i][j] + bb1;
            o2[(size_t)m*LL + n] = ac2[i][j] + bb2;
        }
    }
}

// ---------------------------------------------------------------------------
// Complex GEMM: Cr = Ac@Br + S1*As@Bi ; Ci = Ac@Bi - S1*As@Br (+ optional mag)
// ---------------------------------------------------------------------------
template<int S1, bool WMAG>
__global__ void __launch_bounds__(256)
cgemm(const float* __restrict__ Ac, const float* __restrict__ Asn,
      const float* __restrict__ Br, const float* __restrict__ Bi, int ldbk, int sB,
      float* __restrict__ outR, float* __restrict__ outI, float* __restrict__ outM,
      int ldc, int sC, int M, int N, int K)
{
    __shared__ float Acs[16][68], Ass[16][68], Brs[16][68], Bis[16][68];
    int bz = blockIdx.z;
    const float* BrB = Br + (size_t)bz*sB;
    const float* BiB = Bi + (size_t)bz*sB;
    int m0 = blockIdx.y<<6, n0 = blockIdx.x<<6;
    int tid = threadIdx.x, tx = tid&15, ty = tid>>4;
    float aR[4][4], aI[4][4];
#pragma unroll
    for (int i=0;i<4;i++)
#pragma unroll
        for (int j=0;j<4;j++) { aR[i][j]=0.f; aI[i][j]=0.f; }

    for (int k0 = 0; k0 < K; k0 += 16) {
        {
            int kl = tid&15, ml0 = tid>>4;
#pragma unroll
            for (int i=0;i<4;i++) {
                int ml = ml0 + (i<<4), m = m0+ml, k = k0+kl;
                bool ok = (m<M);
                Acs[kl][ml] = ok ? Ac [(size_t)m*128 + k] : 0.f;
                Ass[kl][ml] = ok ? Asn[(size_t)m*128 + k] : 0.f;
            }
        }
        {
            int nl = tid&63, kl0 = tid>>6;
#pragma unroll
            for (int i=0;i<4;i++) {
                int kl = kl0 + (i<<2), n = n0+nl, k = k0+kl;
                bool ok = (n<N);
                Brs[kl][nl] = ok ? BrB[(size_t)k*ldbk + n] : 0.f;
                Bis[kl][nl] = ok ? BiB[(size_t)k*ldbk + n] : 0.f;
            }
        }
        __syncthreads();
#pragma unroll
        for (int kk=0; kk<16; kk++) {
            float4 acv = *(const float4*)&Acs[kk][ty<<2];
            float4 asv = *(const float4*)&Ass[kk][ty<<2];
            float4 brv = *(const float4*)&Brs[kk][tx<<2];
            float4 biv = *(const float4*)&Bis[kk][tx<<2];
            float ac[4]={acv.x,acv.y,acv.z,acv.w};
            float as[4]={asv.x,asv.y,asv.z,asv.w};
            float br[4]={brv.x,brv.y,brv.z,brv.w};
            float bi[4]={biv.x,biv.y,biv.z,biv.w};
            float sbi[4], sbr[4];
#pragma unroll
            for (int j=0;j<4;j++) {
                sbi[j] = (S1>0) ? bi[j] : -bi[j];
                sbr[j] = (S1>0) ? -br[j] : br[j];
            }
#pragma unroll
            for (int i=0;i<4;i++)
#pragma unroll
                for (int j=0;j<4;j++) {
                    aR[i][j] = fmaf(as[i], sbi[j], fmaf(ac[i], br[j], aR[i][j]));
                    aI[i][j] = fmaf(as[i], sbr[j], fmaf(ac[i], bi[j], aI[i][j]));
                }
        }
        __syncthreads();
    }
    float* oR = outR + (size_t)bz*sC;
    float* oI = outI + (size_t)bz*sC;
    float* oM = WMAG ? (outM + (size_t)bz*sC) : outR;
#pragma unroll
    for (int i=0;i<4;i++) {
        int m = m0 + (ty<<2) + i;
        if (m >= M) continue;
#pragma unroll
        for (int j=0;j<4;j++) {
            int n = n0 + (tx<<2) + j;
            if (n >= N) continue;
            float r = aR[i][j], im = aI[i][j];
            oR[(size_t)m*ldc + n] = r;
            oI[(size_t)m*ldc + n] = im;
            if (WMAG) oM[(size_t)m*ldc + n] = sqrtf(r*r + im*im);
        }
    }
}

// Complex Nyquist column (kf=64): warp per output u; writes re, im (+mag).
template<int S1, bool WMAG>
__global__ void cnyq_k(const float* __restrict__ Ac, const float* __restrict__ Asn,
                       const float* __restrict__ Br, const float* __restrict__ Bi,
                       int ldb, int sB,
                       float* __restrict__ outR, float* __restrict__ outI,
                       float* __restrict__ outM, int sC)
{
    int w = (blockIdx.x*256 + threadIdx.x) >> 5;
    int lane = threadIdx.x & 31;
    int img = w >> 7, u = w & 127;
    const float* br = Br + (size_t)img*sB;
    const float* bi = Bi + (size_t)img*sB;
    float sr = 0.f, si = 0.f;
#pragma unroll
    for (int kk=0; kk<4; kk++) {
        int k = lane + kk*32;
        float ac = Ac[u*128+k], as = Asn[u*128+k];
        float vr = br[(size_t)k*ldb], vi = bi[(size_t)k*ldb];
        sr += ac*vr + ((S1>0) ? as*vi : -as*vi);
        si += ac*vi - ((S1>0) ? as*vr : -as*vr);
    }
#pragma unroll
    for (int o=16; o>=1; o>>=1) {
        sr += __shfl_xor_sync(0xffffffffu, sr, o);
        si += __shfl_xor_sync(0xffffffffu, si, o);
    }
    if (lane == 0) {
        size_t idx = (size_t)img*sC + u*65 + 64;
        outR[idx] = sr;
        outI[idx] = si;
        if (WMAG) outM[idx] = sqrtf(sr*sr + si*si);
    }
}

// rfft columns 128,129 of the 130-wide row transform, warp-per-output.
__global__ void rfft_tail_k(const float* __restrict__ x, float* __restrict__ RT)
{
    int w = (blockIdx.x*256 + threadIdx.x) >> 5;
    int lane = threadIdx.x & 31;
    int row = w >> 1, j = 128 + (w & 1);
    const float* xr = x + (size_t)row*128;
    float s = 0.f;
#pragma unroll
    for (int kk=0; kk<4; kk++) {
        int k = lane + kk*32;
        s += xr[k]*d_TW1[k*130+j];
    }
#pragma unroll
    for (int o=16; o>=1; o>>=1) s += __shfl_xor_sync(0xffffffffu, s, o);
    if (lane == 0) RT[(size_t)row*130 + j] = s;
}

__global__ void conv_silu_k(const float* __restrict__ xz, const float* __restrict__ cw,
                            const float* __restrict__ cb, float* __restrict__ xc)
{
    int idx = blockIdx.x*256 + threadIdx.x;
    if (idx >= BL*DI) return;
    int d = idx & 127, bl = idx >> 7, l = bl & (LL-1);
    size_t base = (size_t)bl*256 + d;
    float acc = cb[d];
#pragma unroll
    for (int k=0;k<4;k++) {
        int lsrc = l - 3 + k;
        float v = (lsrc >= 0) ? xz[base + (size_t)(k-3)*256] : 0.f;
        acc = fmaf(cw[d*4+k], v, acc);
    }
    float sig = 1.f/(1.f+__expf(-acc));
    xc[idx] = acc*sig;
}

__global__ void dt_proj_k(const float* __restrict__ dbc, const float* __restrict__ Wdt,
                          const float* __restrict__ bdt, float* __restrict__ dt)
{
    int idx = blockIdx.x*256 + threadIdx.x;
    if (idx >= BL*DI) return;
    int d = idx & 127, bl = idx >> 7;
    const float* row = dbc + (size_t)bl*36;
    float s = bdt[d];
#pragma unroll
    for (int r=0;r<4;r++) s = fmaf(row[r], Wdt[r*128+d], s);
    dt[idx] = (s > 20.f) ? s : log1pf(__expf(s));
}

__global__ void scan1_k(const float* __restrict__ dt, const float* __restrict__ xc,
                        const float* __restrict__ dbc, const float* __restrict__ A_log,
                        float* __restrict__ hloc, float* __restrict__ cdout)
{
    int warp = threadIdx.x >> 5;
    int wg   = (blockIdx.x<<3) + warp;
    int lane = threadIdx.x & 31;
    int s = lane & 15, half = lane >> 4;
    int dpair = wg & 63, chunk = (wg>>6) & 63, b = wg>>12;
    int d = (dpair<<1) + half;
    float Aval = -__expf(A_log[d*16+s]);
    float h = 0.f, cd = 0.f;
    size_t rowbase = (size_t)b*LL + (chunk<<8);
    const float* dtp = dt  + rowbase*128 + d;
    const float* xcp = xc  + rowbase*128 + d;
    const float* bp  = dbc + rowbase*36 + 4 + s;
#pragma unroll 8
    for (int t=0;t<CHKS;t++) {
        float dtv = dtp[t*128], xcv = xcp[t*128], Bv = bp[t*36];
        h = fmaf(h, __expf(dtv*Aval), dtv*xcv*Bv);
        cd += dtv;
    }
    int cidx = (b*128+d)*NCHK + chunk;
    hloc[cidx*16+s] = h;
    if (s == 0 ) cdout[cidx] = cd;
}

__global__ void carry_k(const float* __restrict__ hloc, const float* __restrict__ cd,
                        const float* __restrict__ A_log, float* __restrict__ Hst)
{
    int idx = blockIdx.x*256 + threadIdx.x;
    if (idx >= BB*DI*DS) return;
    int s = idx & 15, d = (idx>>4)&127, b = idx>>11;
    float Aval = -__expf(A_log[d*16+s]);
    float H = 0.f;
    int base = (b*128+d)*NCHK;
    for (int c=0;c<NCHK;c++) {
        Hst[(base+c)*16+s] = H;
        H = fmaf(H, __expf(Aval*cd[base+c]), hloc[(base+c)*16+s]);
    }
}

__global__ void scan2_k(const float* __restrict__ dt, const float* __restrict__ xc,
                        const float* __restrict__ dbc, const float* __restrict__ A_log,
                        const float* __restrict__ Hst, const float* __restrict__ xz,
                        const float* __restrict__ Dvec, float* __restrict__ ygt)
{
    __shared__ float shy[8][2][CHKS];
    int warp = threadIdx.x >> 5;
    int wg   = (blockIdx.x<<3) + warp;
    int lane = threadIdx.x & 31;
    int s = lane & 15, half = lane >> 4;
    int dpair = wg & 63, chunk = (wg>>6) & 63, b = wg>>12;
    int d = (dpair<<1) + half;
    float Aval = -__expf(A_log[d*16+s]);
    float h = Hst[((b*128+d)*NCHK + chunk)*16 + s];
    float Dv = Dvec[d];
    int t0 = chunk<<8;
    size_t rowbase = (size_t)b*LL + t0;
    const float* dtp = dt  + rowbase*128 + d;
    const float* xcp = xc  + rowbase*128 + d;
    const float* bp  = dbc + rowbase*36 + 4 + s;
    const float* cp  = dbc + rowbase*36 + 20 + s;
    const float* zp  = xz  + rowbase*256 + 128 + d;
#pragma unroll 4
    for (int t=0;t<CHKS;t++) {
        float dtv = dtp[t*128], xcv = xcp[t*128], Bv = bp[t*36], Cv = cp[t*36];
        h = fmaf(h, __expf(dtv*Aval), dtv*xcv*Bv);
        float p = h*Cv;
        p += __shfl_xor_sync(0xffffffffu, p, 1);
        p += __shfl_xor_sync(0xffffffffu, p, 2);
        p += __shfl_xor_sync(0xffffffffu, p, 4);
        p += __shfl_xor_sync(0xffffffffu, p, 8);
        if (s == 0) {
            float zv = zp[(size_t)t*256];
            float y = fmaf(xcv, Dv, p);
            float sig = 1.f/(1.f+__expf(-zv));
            shy[warp][half][t] = y*zv*sig;
        }
    }
    __syncwarp();
#pragma unroll
    for (int r=0;r<2;r++) {
        int dd = (dpair<<1) + r;
        float* dst = ygt + ((size_t)b*128 + dd)*LL + t0;
        for (int t=lane;t<CHKS;t+=32) dst[t] = shy[warp][r][t];
    }
}

__global__ void phase_k(const float* __restrict__ re, const float* __restrict__ im,
                        const float* __restrict__ mg, const float* __restrict__ M2,
                        float* __restrict__ Zr, float* __restrict__ Zi)
{
    int i = blockIdx.x*256 + threadIdx.x;
    if (i >= NIMG*FPIX) return;
    float m = mg[i], m2 = M2[i];
    if (m > 1e-20f) {
        float sc = m2/m;
        Zr[i] = re[i]*sc; Zi[i] = im[i]*sc;
    } else { Zr[i] = m2; Zi[i] = 0.f; }
}

static void G(const float* A, const float* A2, int lam, int lak, int sA,
              const float* B, const float* B2, int lbk, int lbn, int sB,
              float* C, int ldc, int sC, int M, int N, int K, int batch,
              const float* bias, int bm, int relu)
{
    dim3 grid((N+63)>>6, (M+63)>>6, batch);
    if (A2) sgemm<true,4 ><<<grid,256>>>(A,A2,lam,lak,sA,B,B2,lbk,lbn,sB,C,ldc,sC,M,N,K,bias,bm,relu);
    else    sgemm<false,4><<<grid,256>>>(A,nullptr,lam,lak,sA,B,nullptr,lbk,lbn,sB,C,ldc,sC,M,N,K,bias,bm,relu);
}

static void G8(const float* A, int lam, int lak, int sA,
               const float* B, int lbk, int lbn, int sB,
               float* C, int ldc, int sC, int M, int N, int K, int batch,
               const float* bias, int bm, int relu)
{
    dim3 grid((N+63)>>6, (M+127)>>7, batch);
    sgemm<false,8><<<grid,256>>>(A,nullptr,lam,lak,sA,B,nullptr,lbk,lbn,sB,C,ldc,sC,M,N,K,bias,bm,relu);
}

extern "C" void kernel_launch(void* const* d_in, const int* in_sizes, int n_in,
                              void* d_out, int out_size)
{
    const float* x      = (const float*)d_in[0];
    const float* W_in   = (const float*)d_in[1];
    const float* conv_w = (const float*)d_in[2];
    const float* conv_b = (const float*)d_in[3];
    const float* W_xproj= (const float*)d_in[4];
    const float* W_dt   = (const float*)d_in[5];
    const float* b_dt   = (const float*)d_in[6];
    const float* A_log  = (const float*)d_in[7];
    const float* Dvec   = (const float*)d_in[8];
    const float* W_out  = (const float*)d_in[9];
    const float* Wf1    = (const float*)d_in[10];
    const float* bf1    = (const float*)d_in[11];
    const float* Wf2    = (const float*)d_in[12];
    const float* bf2    = (const float*)d_in[13];
    const float* W_enh  = (const float*)d_in[14];
    const float* b_enh  = (const float*)d_in[15];
    const float* W_seg  = (const float*)d_in[16];
    const float* b_seg  = (const float*)d_in[17];
    float* out = (float*)d_out;

    void* pv;
    cudaGetSymbolAddress(&pv, d_xz);   float* p_xz  = (float*)pv;
    cudaGetSymbolAddress(&pv, d_xc);   float* p_xc  = (float*)pv;
    cudaGetSymbolAddress(&pv, d_dbc);  float* p_dbc = (float*)pv;
    cudaGetSymbolAddress(&pv, d_dt);   float* p_dt  = (float*)pv;
    cudaGetSymbolAddress(&pv, d_hloc); float* p_hl  = (float*)pv;
    cudaGetSymbolAddress(&pv, d_cd);   float* p_cd  = (float*)pv;
    cudaGetSymbolAddress(&pv, d_Hst);  float* p_Hs  = (float*)pv;
    cudaGetSymbolAddress(&pv, d_ygt);  float* p_yg  = (float*)pv;
    cudaGetSymbolAddress(&pv, d_xsp);  float* p_xsp = (float*)pv;
    cudaGetSymbolAddress(&pv, d_RT);   float* p_RT  = (float*)pv;
    cudaGetSymbolAddress(&pv, d_Cre);  float* p_Cre = (float*)pv;
    cudaGetSymbolAddress(&pv, d_Cim);  float* p_Cim = (float*)pv;
    cudaGetSymbolAddress(&pv, d_mag);  float* p_mag = (float*)pv;
    cudaGetSymbolAddress(&pv, d_M1);   float* p_M1  = (float*)pv;
    cudaGetSymbolAddress(&pv, d_M2);   float* p_M2  = (float*)pv;
    cudaGetSymbolAddress(&pv, d_Zr);   float* p_Zr  = (float*)pv;
    cudaGetSymbolAddress(&pv, d_Zi);   float* p_Zi  = (float*)pv;
    cudaGetSymbolAddress(&pv, d_Yr);   float* p_Yr  = (float*)pv;
    cudaGetSymbolAddress(&pv, d_Yi);   float* p_Yi  = (float*)pv;
    cudaGetSymbolAddress(&pv, d_xfr);  float* p_xfr = (float*)pv;
    cudaGetSymbolAddress(&pv, d_TW1);  float* p_TW1 = (float*)pv;
    cudaGetSymbolAddress(&pv, d_TCOS); float* p_TC  = (float*)pv;
    cudaGetSymbolAddress(&pv, d_TSIN); float* p_TS  = (float*)pv;
    cudaGetSymbolAddress(&pv, d_TSINN);float* p_TSN = (float*)pv;
    cudaGetSymbolAddress(&pv, d_IRW1); float* p_I1  = (float*)pv;
    cudaGetSymbolAddress(&pv, d_IRW2); float* p_I2  = (float*)pv;

    gen_tables<<<65, 256>>>();

    // ---- Mamba branch ----
    // xz[b] (L x 256) = xf[b] (L x 64) @ W_in ; xf[m,k] = x[b, k*L + m]
    G8(x, 1, LL, CC*LL,  W_in, 256,1, 0,  p_xz, 256, LL*256,  LL, 256, CC, BB, 0,0,0);
    conv_silu_k<<<(BL*DI+255)/256,256>>>(p_xz, conv_w, conv_b, p_xc);
    // dbc (BL x 36) = xc (BL x 128) @ W_xproj
    G8(p_xc, 128,1,0,  W_xproj, 36,1,0,  p_dbc, 36,0,  BL, 36, 128, 1, 0,0,0);
    dt_proj_k<<<(BL*DI+255)/256,256>>>(p_dbc, W_dt, b_dt, p_dt);
    scan1_k<<<2048,256>>>(p_dt, p_xc, p_dbc, A_log, p_hl, p_cd);
    carry_k<<<32,256>>>(p_hl, p_cd, A_log, p_Hs);
    scan2_k<<<2048,256>>>(p_dt, p_xc, p_dbc, A_log, p_Hs, p_xz, Dvec, p_yg);
    // x_spatial channel-major: xsp[b](64 x L) = W_out^T (64x128) @ ygt[b](128 x L)
    G(W_out,0, 1, CC, 0,  p_yg,0, LL,1, DI*LL,  p_xsp, LL, CC*LL,  CC, LL, DI, BB, 0,0,0);

    // ---- Frequency branch ----
    // row rfft: RT (32768 x 128) = x (32768 x 128) @ TW1[:, :128]; cols 128-129 via tail kernel
    G8(x, 128,1,0,  p_TW1, 130,1,0,  p_RT, 130,0,  32768, 128, 128, 1, 0,0,0);
    rfft_tail_k<<<8192,256>>>(x, p_RT);
    // column FFT per image: ONE complex GEMM (re+im+mag) over cols 0-63, cnyq for col 64.
    {
        dim3 grid(1, 2, NIMG);
        cgemm<1,true><<<grid,256>>>(p_TC, p_TS, p_RT, p_RT+65, 130, 128*130,
                                    p_Cre, p_Cim, p_mag, NKF, FPIX, 128, 64, 128);
    }
    cnyq_k<1,true><<<4096,256>>>(p_TC, p_TS, p_RT+64, p_RT+129, 130, 128*130,
                                 p_Cre, p_Cim, p_mag, FPIX);
    // channel mix per batch: M1 = relu(Wf1 @ mag + bf1); M2 = Wf2 @ M1 + bf2
    G(Wf1,0, CC,1,0,  p_mag,0, FPIX,1, CC*FPIX,  p_M1, FPIX, CC*FPIX,  CC, FPIX, CC, BB, bf1, 2, 1);
    G(Wf2,0, CC,1,0,  p_M1,0,  FPIX,1, CC*FPIX,  p_M2, FPIX, CC*FPIX,  CC, FPIX, CC, BB, bf2, 2, 0);
    phase_k<<<(NIMG*FPIX+255)/256,256>>>(p_Cre, p_Cim, p_mag, p_M2, p_Zr, p_Zi);
    // inverse column FFT: ONE complex GEMM (S1 = -1)
    {
        dim3 grid(1, 2, NIMG);
        cgemm<-1,false><<<grid,256>>>(p_TC, p_TS, p_Zr, p_Zi, NKF, FPIX,
                                      p_Yr, p_Yi, nullptr, NKF, FPIX, 128, 64, 128);
    }
    cnyq_k<-1,false><<<4096,256>>>(p_TC, p_TS, p_Zr+64, p_Zi+64, NKF, FPIX,
                                   p_Yr, p_Yi, nullptr, FPIX);
    // irfft rows + fused residual add of x_spatial:
    G(p_Yr, p_Yi, NKF,1, FPIX,  p_I1, p_I2, 128,1, 0,  p_xfr, 128, LL,  128, 128, NKF, NIMG, p_xsp, 3, 0);

    // ---- Heads: fused dual-output GEMM ----
    {
        dim3 grid(LL/64, 1, BB);
        head2_k<<<grid,256>>>(W_enh, W_seg, p_xfr, CC*LL, b_enh, b_seg,
                              out, out + BB*CC*LL, CC*LL);
    }
}